// round 3
// baseline (speedup 1.0000x reference)
#include <cuda_runtime.h>
#include <math.h>

// Problem constants
#define NB 8
#define CH 512
#define HH 48
#define WW 192
#define NTOK (NB*HH*WW)      // 73728 tokens
#define C3 (3*CH)            // 1536
#define C4 (4*CH)            // 2048

// Scratch (static device allocations; no cudaMalloc allowed)
__device__ float g_x  [(size_t)NTOK * CH];   // residual stream, token-major (b,h,w) x C
__device__ float g_ln [(size_t)NTOK * CH];   // layernorm output
__device__ float g_qkv[(size_t)NTOK * C3];   // de-interleaved [q(512)|k(512)|v(512)]
__device__ float g_ctx[(size_t)NTOK * CH];   // attention context
__device__ float g_h  [(size_t)NTOK * C4];   // MLP hidden

// ---------------------------------------------------------------------------
// Transpose in: x(B,C,H,W) -> X[t= b*H*W + h*W + w][c]
// ---------------------------------------------------------------------------
__global__ void transpose_in_kernel(const float* __restrict__ x, float* __restrict__ X)
{
    __shared__ float tile[32][33];
    int bh = blockIdx.z; int b = bh / HH, h = bh % HH;
    int w0 = blockIdx.x * 32, c0 = blockIdx.y * 32;
#pragma unroll
    for (int r = 0; r < 4; r++) {
        int c = c0 + threadIdx.y + r * 8;
        tile[threadIdx.y + r * 8][threadIdx.x] =
            x[(((size_t)b * CH + c) * HH + h) * WW + w0 + threadIdx.x];
    }
    __syncthreads();
#pragma unroll
    for (int r = 0; r < 4; r++) {
        int w = w0 + threadIdx.y + r * 8;
        X[(((size_t)b * HH + h) * WW + w) * CH + c0 + threadIdx.x] =
            tile[threadIdx.x][threadIdx.y + r * 8];
    }
}

// Transpose out: X[t][c] -> out(B,C,H,W)
__global__ void transpose_out_kernel(const float* __restrict__ X, float* __restrict__ out)
{
    __shared__ float tile[32][33];
    int bh = blockIdx.z; int b = bh / HH, h = bh % HH;
    int w0 = blockIdx.x * 32, c0 = blockIdx.y * 32;
#pragma unroll
    for (int r = 0; r < 4; r++) {
        int w = w0 + threadIdx.y + r * 8;
        tile[threadIdx.y + r * 8][threadIdx.x] =
            X[(((size_t)b * HH + h) * WW + w) * CH + c0 + threadIdx.x];
    }
    __syncthreads();
#pragma unroll
    for (int r = 0; r < 4; r++) {
        int c = c0 + threadIdx.y + r * 8;
        out[(((size_t)b * CH + c) * HH + h) * WW + w0 + threadIdx.x] =
            tile[threadIdx.x][threadIdx.y + r * 8];
    }
}

// ---------------------------------------------------------------------------
// Row LayerNorm (C=512), 128 threads/row, float4 vectorized
// ---------------------------------------------------------------------------
__global__ void ln_kernel(const float* __restrict__ X, float* __restrict__ Y,
                          const float* __restrict__ g, const float* __restrict__ b)
{
    __shared__ float red[8];
    size_t t = blockIdx.x;
    float4 v = ((const float4*)(X + t * CH))[threadIdx.x];
    float s = v.x + v.y + v.z + v.w;
    float q = v.x * v.x + v.y * v.y + v.z * v.z + v.w * v.w;
#pragma unroll
    for (int o = 16; o > 0; o >>= 1) {
        s += __shfl_xor_sync(0xffffffffu, s, o);
        q += __shfl_xor_sync(0xffffffffu, q, o);
    }
    int warp = threadIdx.x >> 5;
    if ((threadIdx.x & 31) == 0) { red[warp] = s; red[warp + 4] = q; }
    __syncthreads();
    s = red[0] + red[1] + red[2] + red[3];
    q = red[4] + red[5] + red[6] + red[7];
    float mean = s * (1.0f / CH);
    float var  = q * (1.0f / CH) - mean * mean;
    float rs = rsqrtf(var + 1e-5f);
    float4 gg = ((const float4*)g)[threadIdx.x];
    float4 bb = ((const float4*)b)[threadIdx.x];
    float4 o;
    o.x = (v.x - mean) * rs * gg.x + bb.x;
    o.y = (v.y - mean) * rs * gg.y + bb.y;
    o.z = (v.z - mean) * rs * gg.z + bb.z;
    o.w = (v.w - mean) * rs * gg.w + bb.w;
    ((float4*)(Y + t * CH))[threadIdx.x] = o;
}

// ---------------------------------------------------------------------------
// GEMM: C[M,Nn] = A[M,K] @ W[Nn,K]^T  (both K-contiguous, "NT")
// PERM_QKV: output col j uses weight row (j%512)*3 + j/512, so the interleaved
//           qkv reshape lands as de-interleaved [q|k|v] blocks.
// ---------------------------------------------------------------------------
template<bool PERM_QKV, bool HAS_BIAS, bool RELU, bool ACCUM>
__global__ __launch_bounds__(256)
void gemm_kernel(const float* __restrict__ A, const float* __restrict__ Wt,
                 const float* __restrict__ bias, float* __restrict__ Cd,
                 int M, int Nn, int K)
{
    constexpr int BM = 128, BN = 64, KC = 16;
    __shared__ float As[KC][BM];
    __shared__ float Bs[KC][BN];
    int tid = threadIdx.x;
    int m0 = blockIdx.y * BM, n0 = blockIdx.x * BN;
    int tm = tid >> 4, tn = tid & 15;
    float acc[8][4];
#pragma unroll
    for (int u = 0; u < 8; u++)
#pragma unroll
        for (int v = 0; v < 4; v++) acc[u][v] = 0.0f;

    for (int kc = 0; kc < K; kc += KC) {
#pragma unroll
        for (int l = 0; l < 2; l++) {
            int idx = tid + l * 256;
            int row = idx >> 2, kq = idx & 3;
            float4 v = *(const float4*)(A + (size_t)(m0 + row) * K + kc + kq * 4);
            As[kq * 4 + 0][row] = v.x;
            As[kq * 4 + 1][row] = v.y;
            As[kq * 4 + 2][row] = v.z;
            As[kq * 4 + 3][row] = v.w;
        }
        {
            int row = tid >> 2, kq = tid & 3;
            int j = n0 + row;
            int wr = PERM_QKV ? ((j & 511) * 3 + (j >> 9)) : j;
            float4 v = *(const float4*)(Wt + (size_t)wr * K + kc + kq * 4);
            Bs[kq * 4 + 0][row] = v.x;
            Bs[kq * 4 + 1][row] = v.y;
            Bs[kq * 4 + 2][row] = v.z;
            Bs[kq * 4 + 3][row] = v.w;
        }
        __syncthreads();
#pragma unroll
        for (int k = 0; k < KC; k++) {
            float a[8], bb[4];
#pragma unroll
            for (int u = 0; u < 8; u++) a[u] = As[k][tm * 8 + u];
#pragma unroll
            for (int v = 0; v < 4; v++) bb[v] = Bs[k][tn * 4 + v];
#pragma unroll
            for (int u = 0; u < 8; u++)
#pragma unroll
                for (int v = 0; v < 4; v++) acc[u][v] += a[u] * bb[v];
        }
        __syncthreads();
    }

    float4 bv = make_float4(0.f, 0.f, 0.f, 0.f);
    if (HAS_BIAS) bv = *(const float4*)(bias + n0 + tn * 4);
#pragma unroll
    for (int u = 0; u < 8; u++) {
        size_t off = (size_t)(m0 + tm * 8 + u) * Nn + n0 + tn * 4;
        float t0 = acc[u][0], t1 = acc[u][1], t2 = acc[u][2], t3 = acc[u][3];
        if (HAS_BIAS) { t0 += bv.x; t1 += bv.y; t2 += bv.z; t3 += bv.w; }
        if (RELU) {
            t0 = fmaxf(t0, 0.f); t1 = fmaxf(t1, 0.f);
            t2 = fmaxf(t2, 0.f); t3 = fmaxf(t3, 0.f);
        }
        float4 r;
        if (ACCUM) {
            r = *(const float4*)(Cd + off);
            r.x += t0; r.y += t1; r.z += t2; r.w += t3;
        } else {
            r = make_float4(t0, t1, t2, t3);
        }
        *(float4*)(Cd + off) = r;
    }
}

// ---------------------------------------------------------------------------
// Axial attention. qkv layout per token: [q(512)|k(512)|v(512)].
// AXIS_H: instances (b,w), rows t(h)=b*H*W + h*W + w  (stride W)
// else   : instances (b,h), rows t(w)=(b*H+h)*W + w   (stride 1)
// Two passes: S=scale*QK^T in smem -> softmax in-place -> ctx = P@V.
// ---------------------------------------------------------------------------
__device__ __forceinline__ float warpMaxf(float v) {
#pragma unroll
    for (int o = 16; o > 0; o >>= 1) v = fmaxf(v, __shfl_xor_sync(0xffffffffu, v, o));
    return v;
}
__device__ __forceinline__ float warpSumf(float v) {
#pragma unroll
    for (int o = 16; o > 0; o >>= 1) v += __shfl_xor_sync(0xffffffffu, v, o);
    return v;
}

template<int L, int QT, int JB, bool AXIS_H>
__global__ __launch_bounds__(256)
void attn_kernel(const float* __restrict__ qkv, float* __restrict__ ctx)
{
    constexpr int KC = 16;
    constexpr int II = QT / 16;
    constexpr int JJ = L / 16;
    constexpr int CCH = 64;
    constexpr int NJB = L / JB;

    __shared__ float S [QT][L + 1];
    __shared__ float Qs[KC][QT + 1];
    __shared__ float Ks[KC][L + 1];
    __shared__ float Vs[JB][CCH + 4];

    int tid = threadIdx.x;
    size_t base; int rstride;
    if (AXIS_H) {
        int b = blockIdx.y / WW, w = blockIdx.y % WW;
        base = (size_t)b * HH * WW + w; rstride = WW;
    } else {
        base = (size_t)blockIdx.y * WW; rstride = 1;
    }
    int q0 = blockIdx.x * QT;
    int ty = tid >> 4, tx = tid & 15;

    float acc[II][JJ];
#pragma unroll
    for (int i = 0; i < II; i++)
#pragma unroll
        for (int j = 0; j < JJ; j++) acc[i][j] = 0.0f;

    // ---- Pass 1: S = Q K^T ----
    for (int kc = 0; kc < CH; kc += KC) {
        for (int idx = tid; idx < QT * KC; idx += 256) {
            int i = idx >> 4, k = idx & 15;
            Qs[k][i] = qkv[(base + (size_t)(q0 + i) * rstride) * C3 + kc + k];
        }
        for (int idx = tid; idx < L * KC; idx += 256) {
            int j = idx >> 4, k = idx & 15;
            Ks[k][j] = qkv[(base + (size_t)j * rstride) * C3 + CH + kc + k];
        }
        __syncthreads();
#pragma unroll
        for (int k = 0; k < KC; k++) {
            float av[II], kv[JJ];
#pragma unroll
            for (int i = 0; i < II; i++) av[i] = Qs[k][ty + 16 * i];
#pragma unroll
            for (int j = 0; j < JJ; j++) kv[j] = Ks[k][tx + 16 * j];
#pragma unroll
            for (int i = 0; i < II; i++)
#pragma unroll
                for (int j = 0; j < JJ; j++) acc[i][j] += av[i] * kv[j];
        }
        __syncthreads();
    }
    const float scale = 0.04419417382415922f;  // 1/sqrt(512)
#pragma unroll
    for (int i = 0; i < II; i++)
#pragma unroll
        for (int j = 0; j < JJ; j++) S[ty + 16 * i][tx + 16 * j] = acc[i][j] * scale;
    __syncthreads();

    // ---- Softmax over keys, one warp per row ----
    int warp = tid >> 5, lane = tid & 31;
    for (int r = warp; r < QT; r += 8) {
        float mx = -1e30f;
        for (int j = lane; j < L; j += 32) mx = fmaxf(mx, S[r][j]);
        mx = warpMaxf(mx);
        float sm = 0.0f;
        for (int j = lane; j < L; j += 32) {
            float e = __expf(S[r][j] - mx);
            S[r][j] = e; sm += e;
        }
        sm = warpSumf(sm);
        float inv = 1.0f / sm;
        for (int j = lane; j < L; j += 32) S[r][j] *= inv;
    }
    __syncthreads();

    // ---- Pass 2: ctx = P @ V ----
    for (int c0 = 0; c0 < CH; c0 += CCH) {
        float acc2[II][4];
#pragma unroll
        for (int i = 0; i < II; i++)
#pragma unroll
            for (int u = 0; u < 4; u++) acc2[i][u] = 0.0f;

        for (int jb = 0; jb < NJB; jb++) {
            for (int idx = tid; idx < JB * CCH; idx += 256) {
                int j = idx >> 6, cl = idx & 63;
                Vs[j][cl] = qkv[(base + (size_t)(jb * JB + j) * rstride) * C3 + 2 * CH + c0 + cl];
            }
            __syncthreads();
#pragma unroll 4
            for (int j = 0; j < JB; j++) {
                float pv[II];
#pragma unroll
                for (int i = 0; i < II; i++) pv[i] = S[ty + 16 * i][jb * JB + j];
                float4 vv = *(const float4*)&Vs[j][tx * 4];
#pragma unroll
                for (int i = 0; i < II; i++) {
                    acc2[i][0] += pv[i] * vv.x;
                    acc2[i][1] += pv[i] * vv.y;
                    acc2[i][2] += pv[i] * vv.z;
                    acc2[i][3] += pv[i] * vv.w;
                }
            }
            __syncthreads();
        }
#pragma unroll
        for (int i = 0; i < II; i++) {
            int qi = ty + 16 * i;
            size_t t = base + (size_t)(q0 + qi) * rstride;
            float4 o = make_float4(acc2[i][0], acc2[i][1], acc2[i][2], acc2[i][3]);
            *(float4*)&ctx[t * CH + c0 + tx * 4] = o;
        }
    }
}

// ---------------------------------------------------------------------------
// Launch
// ---------------------------------------------------------------------------
extern "C" void kernel_launch(void* const* d_in, const int* in_sizes, int n_in,
                              void* d_out, int out_size)
{
    const float* x      = (const float*)d_in[0];
    const float* w_qkv1 = (const float*)d_in[1];
    const float* w_out1 = (const float*)d_in[2];
    const float* w_qkv2 = (const float*)d_in[3];
    const float* w_out2 = (const float*)d_in[4];
    const float* g1 = (const float*)d_in[5],  *b1 = (const float*)d_in[6];
    const float* g2 = (const float*)d_in[7],  *b2 = (const float*)d_in[8];
    const float* g3 = (const float*)d_in[9],  *b3 = (const float*)d_in[10];
    const float* w_fc1 = (const float*)d_in[11], *b_fc1 = (const float*)d_in[12];
    const float* w_fc2 = (const float*)d_in[13], *b_fc2 = (const float*)d_in[14];
    float* out = (float*)d_out;

    float *X, *LN, *QKV, *CTX, *Hb;
    cudaGetSymbolAddress((void**)&X,   g_x);
    cudaGetSymbolAddress((void**)&LN,  g_ln);
    cudaGetSymbolAddress((void**)&QKV, g_qkv);
    cudaGetSymbolAddress((void**)&CTX, g_ctx);
    cudaGetSymbolAddress((void**)&Hb,  g_h);

    dim3 tb(32, 8);
    dim3 tgrid(WW / 32, CH / 32, NB * HH);

    // x -> token-major residual stream
    transpose_in_kernel<<<tgrid, tb>>>(x, X);

    // Block 1: attention along H
    ln_kernel<<<NTOK, 128>>>(X, LN, g1, b1);
    gemm_kernel<true,  false, false, false><<<dim3(C3 / 64, NTOK / 128), 256>>>(LN, w_qkv1, nullptr, QKV, NTOK, C3, CH);
    attn_kernel<48, 48, 48, true><<<dim3(1, NB * WW), 256>>>(QKV, CTX);
    gemm_kernel<false, false, false, true ><<<dim3(CH / 64, NTOK / 128), 256>>>(CTX, w_out1, nullptr, X, NTOK, CH, CH);

    // Block 2: attention along W
    ln_kernel<<<NTOK, 128>>>(X, LN, g2, b2);
    gemm_kernel<true,  false, false, false><<<dim3(C3 / 64, NTOK / 128), 256>>>(LN, w_qkv2, nullptr, QKV, NTOK, C3, CH);
    attn_kernel<192, 32, 32, false><<<dim3(192 / 32, NB * HH), 256>>>(QKV, CTX);
    gemm_kernel<false, false, false, true ><<<dim3(CH / 64, NTOK / 128), 256>>>(CTX, w_out2, nullptr, X, NTOK, CH, CH);

    // MLP
    ln_kernel<<<NTOK, 128>>>(X, LN, g3, b3);
    gemm_kernel<false, true,  true,  false><<<dim3(C4 / 64, NTOK / 128), 256>>>(LN, w_fc1, b_fc1, Hb, NTOK, C4, CH);
    gemm_kernel<false, true,  false, true ><<<dim3(CH / 64, NTOK / 128), 256>>>(Hb, w_fc2, b_fc2, X, NTOK, CH, C4);

    // back to (B,C,H,W)
    transpose_out_kernel<<<tgrid, tb>>>(X, out);
}

// round 6
// speedup vs baseline: 2.8624x; 2.8624x over previous
#include <cuda_runtime.h>
#include <math.h>
#include <stdint.h>

// Problem constants
#define NB 8
#define CH 512
#define HH 48
#define WW 192
#define NTOK (NB*HH*WW)      // 73728 tokens
#define C3 (3*CH)            // 1536
#define C4 (4*CH)            // 2048

// Scratch (static device allocations; no cudaMalloc allowed)
__device__ float g_x  [(size_t)NTOK * CH];   // residual stream
__device__ float g_ln [(size_t)NTOK * CH];   // layernorm output (tf32-rounded)
__device__ float g_qkv[(size_t)NTOK * C3];   // de-interleaved [q|k|v]
__device__ float g_ctx[(size_t)NTOK * CH];   // attention context (tf32-rounded)
__device__ float g_h  [(size_t)NTOK * C4];   // MLP hidden (tf32-rounded)
__device__ float g_wr [4194304];             // tf32-rounded weights

// rounded-weight offsets
#define O_WQ1 0
#define O_WO1 786432
#define O_WQ2 1048576
#define O_WO2 1835008
#define O_FC1 2097152
#define O_FC2 3145728

__device__ __forceinline__ float tf32r(float x) {
    uint32_t u;
    asm("cvt.rna.tf32.f32 %0, %1;" : "=r"(u) : "f"(x));
    return __uint_as_float(u);
}

// ---------------------------------------------------------------------------
// Weight rounding (fp32 -> tf32-in-fp32), vectorized
// ---------------------------------------------------------------------------
__global__ void rnd_kernel(const float* __restrict__ in, float* __restrict__ out, int n4)
{
    int i = blockIdx.x * blockDim.x + threadIdx.x;
    if (i < n4) {
        float4 v = ((const float4*)in)[i];
        v.x = tf32r(v.x); v.y = tf32r(v.y); v.z = tf32r(v.z); v.w = tf32r(v.w);
        ((float4*)out)[i] = v;
    }
}

// ---------------------------------------------------------------------------
// Transposes
// ---------------------------------------------------------------------------
__global__ void transpose_in_kernel(const float* __restrict__ x, float* __restrict__ X)
{
    __shared__ float tile[32][33];
    int bh = blockIdx.z; int b = bh / HH, h = bh % HH;
    int w0 = blockIdx.x * 32, c0 = blockIdx.y * 32;
#pragma unroll
    for (int r = 0; r < 4; r++) {
        int c = c0 + threadIdx.y + r * 8;
        tile[threadIdx.y + r * 8][threadIdx.x] =
            x[(((size_t)b * CH + c) * HH + h) * WW + w0 + threadIdx.x];
    }
    __syncthreads();
#pragma unroll
    for (int r = 0; r < 4; r++) {
        int w = w0 + threadIdx.y + r * 8;
        X[(((size_t)b * HH + h) * WW + w) * CH + c0 + threadIdx.x] =
            tile[threadIdx.x][threadIdx.y + r * 8];
    }
}

__global__ void transpose_out_kernel(const float* __restrict__ X, float* __restrict__ out)
{
    __shared__ float tile[32][33];
    int bh = blockIdx.z; int b = bh / HH, h = bh % HH;
    int w0 = blockIdx.x * 32, c0 = blockIdx.y * 32;
#pragma unroll
    for (int r = 0; r < 4; r++) {
        int w = w0 + threadIdx.y + r * 8;
        tile[threadIdx.y + r * 8][threadIdx.x] =
            X[(((size_t)b * HH + h) * WW + w) * CH + c0 + threadIdx.x];
    }
    __syncthreads();
#pragma unroll
    for (int r = 0; r < 4; r++) {
        int c = c0 + threadIdx.y + r * 8;
        out[(((size_t)b * CH + c) * HH + h) * WW + w0 + threadIdx.x] =
            tile[threadIdx.x][threadIdx.y + r * 8];
    }
}

// ---------------------------------------------------------------------------
// Row LayerNorm (C=512); output rounded to tf32 (it only feeds GEMMs)
// ---------------------------------------------------------------------------
__global__ void ln_kernel(const float* __restrict__ X, float* __restrict__ Y,
                          const float* __restrict__ g, const float* __restrict__ b)
{
    __shared__ float red[8];
    size_t t = blockIdx.x;
    float4 v = ((const float4*)(X + t * CH))[threadIdx.x];
    float s = v.x + v.y + v.z + v.w;
    float q = v.x * v.x + v.y * v.y + v.z * v.z + v.w * v.w;
#pragma unroll
    for (int o = 16; o > 0; o >>= 1) {
        s += __shfl_xor_sync(0xffffffffu, s, o);
        q += __shfl_xor_sync(0xffffffffu, q, o);
    }
    int warp = threadIdx.x >> 5;
    if ((threadIdx.x & 31) == 0) { red[warp] = s; red[warp + 4] = q; }
    __syncthreads();
    s = red[0] + red[1] + red[2] + red[3];
    q = red[4] + red[5] + red[6] + red[7];
    float mean = s * (1.0f / CH);
    float var  = q * (1.0f / CH) - mean * mean;
    float rs = rsqrtf(var + 1e-5f);
    float4 gg = ((const float4*)g)[threadIdx.x];
    float4 bb = ((const float4*)b)[threadIdx.x];
    float4 o;
    o.x = tf32r((v.x - mean) * rs * gg.x + bb.x);
    o.y = tf32r((v.y - mean) * rs * gg.y + bb.y);
    o.z = tf32r((v.z - mean) * rs * gg.z + bb.z);
    o.w = tf32r((v.w - mean) * rs * gg.w + bb.w);
    ((float4*)(Y + t * CH))[threadIdx.x] = o;
}

// ---------------------------------------------------------------------------
// tf32 mma.sync GEMM: C[M,Nn] = A[M,K] @ W[Nn,K]^T (NT, K-contiguous)
// 128x128x32 CTA tile, 8 warps x (64x32), double-buffered cp.async.
// Inputs are pre-rounded to tf32 so in-register truncation is exact.
// ---------------------------------------------------------------------------
#define SROW 36                       // smem row pitch (floats): conflict-free frags
#define ABUF (128*SROW)               // 4608 floats per buffer
#define GEMM_SMEM (4*ABUF*4)          // A[2]+B[2] = 73728 bytes

__device__ __forceinline__ void cp16(uint32_t dst, const float* src) {
    asm volatile("cp.async.cg.shared.global [%0], [%1], 16;" :: "r"(dst), "l"(src));
}

__device__ __forceinline__ void mma8(float* c, const uint32_t* a, const uint32_t* b) {
    asm volatile(
        "mma.sync.aligned.m16n8k8.row.col.f32.tf32.tf32.f32 "
        "{%0,%1,%2,%3}, {%4,%5,%6,%7}, {%8,%9}, {%0,%1,%2,%3};"
        : "+f"(c[0]), "+f"(c[1]), "+f"(c[2]), "+f"(c[3])
        : "r"(a[0]), "r"(a[1]), "r"(a[2]), "r"(a[3]), "r"(b[0]), "r"(b[1]));
}

template<bool PERM, bool HAS_BIAS, bool RELU, bool ACCUM, bool ROUND>
__global__ __launch_bounds__(256, 2)
void mma_gemm(const float* __restrict__ A, const float* __restrict__ Wt,
              const float* __restrict__ bias, float* __restrict__ Cd,
              int M, int Nn, int K)
{
    extern __shared__ float sm[];
    float* AsBase = sm;               // [2][128][SROW]
    float* BsBase = sm + 2 * ABUF;    // [2][128][SROW]
    uint32_t sA0 = (uint32_t)__cvta_generic_to_shared(AsBase);
    uint32_t sB0 = (uint32_t)__cvta_generic_to_shared(BsBase);

    const int tid  = threadIdx.x;
    const int wid  = tid >> 5, lane = tid & 31;
    const int gid  = lane >> 2, tg = lane & 3;
    const int m0   = blockIdx.y * 128, n0 = blockIdx.x * 128;
    const int wm   = (wid >> 2) * 64;       // warp m offset (0,64)
    const int wn   = (wid & 3) * 32;        // warp n offset (0,32,64,96)

    float acc[4][4][4];
#pragma unroll
    for (int mi = 0; mi < 4; mi++)
#pragma unroll
        for (int ni = 0; ni < 4; ni++)
#pragma unroll
            for (int r = 0; r < 4; r++) acc[mi][ni][r] = 0.0f;

    const int NC = K >> 5;

    // async tile loaders: 1024 float4 per matrix per chunk, 4 per thread
    auto loadTiles = [&](int buf, int kc) {
#pragma unroll
        for (int l = 0; l < 4; l++) {
            int idx = tid + l * 256;
            int row = idx >> 3, q = idx & 7;
            uint32_t d = sA0 + (uint32_t)((buf * ABUF + row * SROW + q * 4) * 4);
            cp16(d, A + (size_t)(m0 + row) * K + kc + q * 4);
        }
#pragma unroll
        for (int l = 0; l < 4; l++) {
            int idx = tid + l * 256;
            int row = idx >> 3, q = idx & 7;
            int j = n0 + row;
            int wr = PERM ? ((j & 511) * 3 + (j >> 9)) : j;
            uint32_t d = sB0 + (uint32_t)((buf * ABUF + row * SROW + q * 4) * 4);
            cp16(d, Wt + (size_t)wr * K + kc + q * 4);
        }
    };

    loadTiles(0, 0);
    asm volatile("cp.async.commit_group;");

    for (int c = 0; c < NC; c++) {
        if (c + 1 < NC) {
            loadTiles((c + 1) & 1, (c + 1) << 5);
            asm volatile("cp.async.commit_group;");
            asm volatile("cp.async.wait_group 1;" ::: "memory");
        } else {
            asm volatile("cp.async.wait_group 0;" ::: "memory");
        }
        __syncthreads();

        const float* Ab = AsBase + (c & 1) * ABUF;
        const float* Bb = BsBase + (c & 1) * ABUF;
#pragma unroll
        for (int ks = 0; ks < 4; ks++) {
            const int kb = ks * 8;
            uint32_t a[4][4], b[4][2];
#pragma unroll
            for (int mi = 0; mi < 4; mi++) {
                const float* p0 = Ab + (wm + mi * 16 + gid) * SROW + kb + tg;
                const float* p1 = p0 + 8 * SROW;
                a[mi][0] = __float_as_uint(p0[0]);
                a[mi][1] = __float_as_uint(p1[0]);
                a[mi][2] = __float_as_uint(p0[4]);
                a[mi][3] = __float_as_uint(p1[4]);
            }
#pragma unroll
            for (int ni = 0; ni < 4; ni++) {
                const float* p = Bb + (wn + ni * 8 + gid) * SROW + kb + tg;
                b[ni][0] = __float_as_uint(p[0]);
                b[ni][1] = __float_as_uint(p[4]);
            }
#pragma unroll
            for (int mi = 0; mi < 4; mi++)
#pragma unroll
                for (int ni = 0; ni < 4; ni++)
                    mma8(acc[mi][ni], a[mi], b[ni]);
        }
        __syncthreads();
    }

    // Epilogue: c0,c1 -> (row, col..col+1); c2,c3 -> (row+8, ...)
#pragma unroll
    for (int ni = 0; ni < 4; ni++) {
        int col = n0 + wn + ni * 8 + 2 * tg;
        float2 bv = make_float2(0.f, 0.f);
        if (HAS_BIAS) bv = *(const float2*)(bias + col);
#pragma unroll
        for (int mi = 0; mi < 4; mi++) {
            int row0 = m0 + wm + mi * 16 + gid;
#pragma unroll
            for (int h = 0; h < 2; h++) {
                int row = row0 + h * 8;
                float vx = acc[mi][ni][2 * h + 0];
                float vy = acc[mi][ni][2 * h + 1];
                if (HAS_BIAS) { vx += bv.x; vy += bv.y; }
                if (RELU) { vx = fmaxf(vx, 0.f); vy = fmaxf(vy, 0.f); }
                if (ROUND) { vx = tf32r(vx); vy = tf32r(vy); }
                size_t off = (size_t)row * Nn + col;
                float2 o;
                if (ACCUM) {
                    o = *(const float2*)(Cd + off);
                    o.x += vx; o.y += vy;
                } else {
                    o = make_float2(vx, vy);
                }
                *(float2*)(Cd + off) = o;
            }
        }
    }
}

// ---------------------------------------------------------------------------
// Axial attention (ctx store rounded to tf32; it only feeds the out-proj GEMM)
// ---------------------------------------------------------------------------
__device__ __forceinline__ float warpMaxf(float v) {
#pragma unroll
    for (int o = 16; o > 0; o >>= 1) v = fmaxf(v, __shfl_xor_sync(0xffffffffu, v, o));
    return v;
}
__device__ __forceinline__ float warpSumf(float v) {
#pragma unroll
    for (int o = 16; o > 0; o >>= 1) v += __shfl_xor_sync(0xffffffffu, v, o);
    return v;
}

template<int L, int QT, int JB, bool AXIS_H>
__global__ __launch_bounds__(256)
void attn_kernel(const float* __restrict__ qkv, float* __restrict__ ctx)
{
    constexpr int KC = 16;
    constexpr int II = QT / 16;
    constexpr int JJ = L / 16;
    constexpr int CCH = 64;
    constexpr int NJB = L / JB;

    __shared__ float S [QT][L + 1];
    __shared__ float Qs[KC][QT + 1];
    __shared__ float Ks[KC][L + 1];
    __shared__ float Vs[JB][CCH + 4];

    int tid = threadIdx.x;
    size_t base; int rstride;
    if (AXIS_H) {
        int b = blockIdx.y / WW, w = blockIdx.y % WW;
        base = (size_t)b * HH * WW + w; rstride = WW;
    } else {
        base = (size_t)blockIdx.y * WW; rstride = 1;
    }
    int q0 = blockIdx.x * QT;
    int ty = tid >> 4, tx = tid & 15;

    float acc[II][JJ];
#pragma unroll
    for (int i = 0; i < II; i++)
#pragma unroll
        for (int j = 0; j < JJ; j++) acc[i][j] = 0.0f;

    for (int kc = 0; kc < CH; kc += KC) {
        for (int idx = tid; idx < QT * KC; idx += 256) {
            int i = idx >> 4, k = idx & 15;
            Qs[k][i] = qkv[(base + (size_t)(q0 + i) * rstride) * C3 + kc + k];
        }
        for (int idx = tid; idx < L * KC; idx += 256) {
            int j = idx >> 4, k = idx & 15;
            Ks[k][j] = qkv[(base + (size_t)j * rstride) * C3 + CH + kc + k];
        }
        __syncthreads();
#pragma unroll
        for (int k = 0; k < KC; k++) {
            float av[II], kv[JJ];
#pragma unroll
            for (int i = 0; i < II; i++) av[i] = Qs[k][ty + 16 * i];
#pragma unroll
            for (int j = 0; j < JJ; j++) kv[j] = Ks[k][tx + 16 * j];
#pragma unroll
            for (int i = 0; i < II; i++)
#pragma unroll
                for (int j = 0; j < JJ; j++) acc[i][j] += av[i] * kv[j];
        }
        __syncthreads();
    }
    const float scale = 0.04419417382415922f;  // 1/sqrt(512)
#pragma unroll
    for (int i = 0; i < II; i++)
#pragma unroll
        for (int j = 0; j < JJ; j++) S[ty + 16 * i][tx + 16 * j] = acc[i][j] * scale;
    __syncthreads();

    int warp = tid >> 5, lane = tid & 31;
    for (int r = warp; r < QT; r += 8) {
        float mx = -1e30f;
        for (int j = lane; j < L; j += 32) mx = fmaxf(mx, S[r][j]);
        mx = warpMaxf(mx);
        float sm = 0.0f;
        for (int j = lane; j < L; j += 32) {
            float e = __expf(S[r][j] - mx);
            S[r][j] = e; sm += e;
        }
        sm = warpSumf(sm);
        float inv = 1.0f / sm;
        for (int j = lane; j < L; j += 32) S[r][j] *= inv;
    }
    __syncthreads();

    for (int c0 = 0; c0 < CH; c0 += CCH) {
        float acc2[II][4];
#pragma unroll
        for (int i = 0; i < II; i++)
#pragma unroll
            for (int u = 0; u < 4; u++) acc2[i][u] = 0.0f;

        for (int jb = 0; jb < NJB; jb++) {
            for (int idx = tid; idx < JB * CCH; idx += 256) {
                int j = idx >> 6, cl = idx & 63;
                Vs[j][cl] = qkv[(base + (size_t)(jb * JB + j) * rstride) * C3 + 2 * CH + c0 + cl];
            }
            __syncthreads();
#pragma unroll 4
            for (int j = 0; j < JB; j++) {
                float pv[II];
#pragma unroll
                for (int i = 0; i < II; i++) pv[i] = S[ty + 16 * i][jb * JB + j];
                float4 vv = *(const float4*)&Vs[j][tx * 4];
#pragma unroll
                for (int i = 0; i < II; i++) {
                    acc2[i][0] += pv[i] * vv.x;
                    acc2[i][1] += pv[i] * vv.y;
                    acc2[i][2] += pv[i] * vv.z;
                    acc2[i][3] += pv[i] * vv.w;
                }
            }
            __syncthreads();
        }
#pragma unroll
        for (int i = 0; i < II; i++) {
            int qi = ty + 16 * i;
            size_t t = base + (size_t)(q0 + qi) * rstride;
            float4 o = make_float4(tf32r(acc2[i][0]), tf32r(acc2[i][1]),
                                   tf32r(acc2[i][2]), tf32r(acc2[i][3]));
            *(float4*)&ctx[t * CH + c0 + tx * 4] = o;
        }
    }
}

// ---------------------------------------------------------------------------
// Launch
// ---------------------------------------------------------------------------
extern "C" void kernel_launch(void* const* d_in, const int* in_sizes, int n_in,
                              void* d_out, int out_size)
{
    const float* x      = (const float*)d_in[0];
    const float* w_qkv1 = (const float*)d_in[1];
    const float* w_out1 = (const float*)d_in[2];
    const float* w_qkv2 = (const float*)d_in[3];
    const float* w_out2 = (const float*)d_in[4];
    const float* g1 = (const float*)d_in[5],  *b1 = (const float*)d_in[6];
    const float* g2 = (const float*)d_in[7],  *b2 = (const float*)d_in[8];
    const float* g3 = (const float*)d_in[9],  *b3 = (const float*)d_in[10];
    const float* w_fc1 = (const float*)d_in[11], *b_fc1 = (const float*)d_in[12];
    const float* w_fc2 = (const float*)d_in[13], *b_fc2 = (const float*)d_in[14];
    float* out = (float*)d_out;

    float *X, *LN, *QKV, *CTX, *Hb, *WR;
    cudaGetSymbolAddress((void**)&X,   g_x);
    cudaGetSymbolAddress((void**)&LN,  g_ln);
    cudaGetSymbolAddress((void**)&QKV, g_qkv);
    cudaGetSymbolAddress((void**)&CTX, g_ctx);
    cudaGetSymbolAddress((void**)&Hb,  g_h);
    cudaGetSymbolAddress((void**)&WR,  g_wr);

    cudaFuncSetAttribute(mma_gemm<true,  false, false, false, false>,
                         cudaFuncAttributeMaxDynamicSharedMemorySize, GEMM_SMEM);
    cudaFuncSetAttribute(mma_gemm<false, false, false, true,  false>,
                         cudaFuncAttributeMaxDynamicSharedMemorySize, GEMM_SMEM);
    cudaFuncSetAttribute(mma_gemm<false, true,  true,  false, true >,
                         cudaFuncAttributeMaxDynamicSharedMemorySize, GEMM_SMEM);
    cudaFuncSetAttribute(mma_gemm<false, true,  false, true,  false>,
                         cudaFuncAttributeMaxDynamicSharedMemorySize, GEMM_SMEM);

    // tf32-round the weights once per launch (graph-capturable kernels)
    rnd_kernel<<<(C3*CH/4 + 255)/256, 256>>>(w_qkv1, WR + O_WQ1, C3*CH/4);
    rnd_kernel<<<(CH*CH/4 + 255)/256, 256>>>(w_out1, WR + O_WO1, CH*CH/4);
    rnd_kernel<<<(C3*CH/4 + 255)/256, 256>>>(w_qkv2, WR + O_WQ2, C3*CH/4);
    rnd_kernel<<<(CH*CH/4 + 255)/256, 256>>>(w_out2, WR + O_WO2, CH*CH/4);
    rnd_kernel<<<(C4*CH/4 + 255)/256, 256>>>(w_fc1,  WR + O_FC1, C4*CH/4);
    rnd_kernel<<<(CH*C4/4 + 255)/256, 256>>>(w_fc2,  WR + O_FC2, CH*C4/4);

    dim3 tb(32, 8);
    dim3 tgrid(WW / 32, CH / 32, NB * HH);

    transpose_in_kernel<<<tgrid, tb>>>(x, X);

    // Block 1: attention along H
    ln_kernel<<<NTOK, 128>>>(X, LN, g1, b1);
    mma_gemm<true,  false, false, false, false><<<dim3(C3 / 128, NTOK / 128), 256, GEMM_SMEM>>>(LN, WR + O_WQ1, nullptr, QKV, NTOK, C3, CH);
    attn_kernel<48, 48, 48, true><<<dim3(1, NB * WW), 256>>>(QKV, CTX);
    mma_gemm<false, false, false, true,  false><<<dim3(CH / 128, NTOK / 128), 256, GEMM_SMEM>>>(CTX, WR + O_WO1, nullptr, X, NTOK, CH, CH);

    // Block 2: attention along W
    ln_kernel<<<NTOK, 128>>>(X, LN, g2, b2);
    mma_gemm<true,  false, false, false, false><<<dim3(C3 / 128, NTOK / 128), 256, GEMM_SMEM>>>(LN, WR + O_WQ2, nullptr, QKV, NTOK, C3, CH);
    attn_kernel<192, 32, 32, false><<<dim3(192 / 32, NB * HH), 256>>>(QKV, CTX);
    mma_gemm<false, false, false, true,  false><<<dim3(CH / 128, NTOK / 128), 256, GEMM_SMEM>>>(CTX, WR + O_WO2, nullptr, X, NTOK, CH, CH);

    // MLP
    ln_kernel<<<NTOK, 128>>>(X, LN, g3, b3);
    mma_gemm<false, true,  true,  false, true ><<<dim3(C4 / 128, NTOK / 128), 256, GEMM_SMEM>>>(LN, WR + O_FC1, b_fc1, Hb, NTOK, C4, CH);
    mma_gemm<false, true,  false, true,  false><<<dim3(CH / 128, NTOK / 128), 256, GEMM_SMEM>>>(Hb, WR + O_FC2, b_fc2, X, NTOK, CH, C4);

    transpose_out_kernel<<<tgrid, tb>>>(X, out);
}

// round 9
// speedup vs baseline: 4.5791x; 1.5997x over previous
#include <cuda_runtime.h>
#include <cuda_fp16.h>
#include <math.h>
#include <stdint.h>

// Problem constants
#define NB 8
#define CH 512
#define HH 48
#define WW 192
#define NTOK (NB*HH*WW)      // 73728 tokens
#define C3 (3*CH)            // 1536
#define C4 (4*CH)            // 2048

// Scratch (static device allocations)
__device__ float  g_x  [(size_t)NTOK * CH];   // residual stream (fp32)
__device__ __half g_ln [(size_t)NTOK * CH];   // layernorm output
__device__ __half g_qkv[(size_t)NTOK * C3];   // de-interleaved [q|k|v]
__device__ __half g_ctx[(size_t)NTOK * CH];   // attention context
__device__ __half g_h  [(size_t)NTOK * C4];   // MLP hidden
__device__ __half g_wr [4194304];             // fp16 weights

#define O_WQ1 0
#define O_WO1 786432
#define O_WQ2 1048576
#define O_WO2 1835008
#define O_FC1 2097152
#define O_FC2 3145728

// ---------------------------------------------------------------------------
// fp32 -> fp16 weight conversion
// ---------------------------------------------------------------------------
__global__ void f2h_kernel(const float* __restrict__ in, __half* __restrict__ out, int n4)
{
    int i = blockIdx.x * blockDim.x + threadIdx.x;
    if (i < n4) {
        float4 v = ((const float4*)in)[i];
        ((__half2*)out)[2 * i]     = __floats2half2_rn(v.x, v.y);
        ((__half2*)out)[2 * i + 1] = __floats2half2_rn(v.z, v.w);
    }
}

// ---------------------------------------------------------------------------
// Transposes
// ---------------------------------------------------------------------------
__global__ void transpose_in_kernel(const float* __restrict__ x, float* __restrict__ X)
{
    __shared__ float tile[32][33];
    int bh = blockIdx.z; int b = bh / HH, h = bh % HH;
    int w0 = blockIdx.x * 32, c0 = blockIdx.y * 32;
#pragma unroll
    for (int r = 0; r < 4; r++) {
        int c = c0 + threadIdx.y + r * 8;
        tile[threadIdx.y + r * 8][threadIdx.x] =
            x[(((size_t)b * CH + c) * HH + h) * WW + w0 + threadIdx.x];
    }
    __syncthreads();
#pragma unroll
    for (int r = 0; r < 4; r++) {
        int w = w0 + threadIdx.y + r * 8;
        X[(((size_t)b * HH + h) * WW + w) * CH + c0 + threadIdx.x] =
            tile[threadIdx.x][threadIdx.y + r * 8];
    }
}

__global__ void transpose_out_kernel(const float* __restrict__ X, float* __restrict__ out)
{
    __shared__ float tile[32][33];
    int bh = blockIdx.z; int b = bh / HH, h = bh % HH;
    int w0 = blockIdx.x * 32, c0 = blockIdx.y * 32;
#pragma unroll
    for (int r = 0; r < 4; r++) {
        int w = w0 + threadIdx.y + r * 8;
        tile[threadIdx.y + r * 8][threadIdx.x] =
            X[(((size_t)b * HH + h) * WW + w) * CH + c0 + threadIdx.x];
    }
    __syncthreads();
#pragma unroll
    for (int r = 0; r < 4; r++) {
        int c = c0 + threadIdx.y + r * 8;
        out[(((size_t)b * CH + c) * HH + h) * WW + w0 + threadIdx.x] =
            tile[threadIdx.x][threadIdx.y + r * 8];
    }
}

// ---------------------------------------------------------------------------
// Row LayerNorm (C=512); fp32 in, fp16 out (feeds GEMMs only)
// ---------------------------------------------------------------------------
__global__ void ln_kernel(const float* __restrict__ X, __half* __restrict__ Y,
                          const float* __restrict__ g, const float* __restrict__ b)
{
    __shared__ float red[8];
    size_t t = blockIdx.x;
    float4 v = ((const float4*)(X + t * CH))[threadIdx.x];
    float s = v.x + v.y + v.z + v.w;
    float q = v.x * v.x + v.y * v.y + v.z * v.z + v.w * v.w;
#pragma unroll
    for (int o = 16; o > 0; o >>= 1) {
        s += __shfl_xor_sync(0xffffffffu, s, o);
        q += __shfl_xor_sync(0xffffffffu, q, o);
    }
    int warp = threadIdx.x >> 5;
    if ((threadIdx.x & 31) == 0) { red[warp] = s; red[warp + 4] = q; }
    __syncthreads();
    s = red[0] + red[1] + red[2] + red[3];
    q = red[4] + red[5] + red[6] + red[7];
    float mean = s * (1.0f / CH);
    float var  = q * (1.0f / CH) - mean * mean;
    float rs = rsqrtf(var + 1e-5f);
    float4 gg = ((const float4*)g)[threadIdx.x];
    float4 bb = ((const float4*)b)[threadIdx.x];
    __half2* Yp = (__half2*)(Y + t * CH);
    Yp[2 * threadIdx.x]     = __floats2half2_rn((v.x - mean) * rs * gg.x + bb.x,
                                                (v.y - mean) * rs * gg.y + bb.y);
    Yp[2 * threadIdx.x + 1] = __floats2half2_rn((v.z - mean) * rs * gg.z + bb.z,
                                                (v.w - mean) * rs * gg.w + bb.w);
}

// ---------------------------------------------------------------------------
// fp16 mma.sync GEMM: C[M,Nn] = A[M,K] @ W[Nn,K]^T (NT, K-contiguous halves)
// CTA 128x128x64(half), 8 warps x (64x32), ldmatrix from swizzled smem,
// cp.async double buffer, fp32 accumulators.
// ---------------------------------------------------------------------------
#define GEMM_SMEM 65536   // A[2]:32KB + B[2]:32KB (128 rows x 128B each)

__device__ __forceinline__ void cp16(uint32_t dst, const void* src) {
    asm volatile("cp.async.cg.shared.global [%0], [%1], 16;" :: "r"(dst), "l"(src));
}

#define LDSM_X4(R, addr) \
    asm volatile("ldmatrix.sync.aligned.m8n8.x4.shared.b16 {%0,%1,%2,%3}, [%4];" \
                 : "=r"((R)[0]), "=r"((R)[1]), "=r"((R)[2]), "=r"((R)[3]) : "r"(addr))

__device__ __forceinline__ void mma16816(float* c, const uint32_t* a, const uint32_t* b) {
    asm volatile(
        "mma.sync.aligned.m16n8k16.row.col.f32.f16.f16.f32 "
        "{%0,%1,%2,%3}, {%4,%5,%6,%7}, {%8,%9}, {%0,%1,%2,%3};"
        : "+f"(c[0]), "+f"(c[1]), "+f"(c[2]), "+f"(c[3])
        : "r"(a[0]), "r"(a[1]), "r"(a[2]), "r"(a[3]), "r"(b[0]), "r"(b[1]));
}

template<bool PERM, bool HAS_BIAS, bool RELU, bool ACCUM, bool OUT_HALF>
__global__ __launch_bounds__(256, 2)
void mma_gemm(const __half* __restrict__ A, const __half* __restrict__ Wt,
              const float* __restrict__ bias, void* __restrict__ CdV,
              int M, int Nn, int K)
{
    extern __shared__ char smc[];
    uint32_t sA0 = (uint32_t)__cvta_generic_to_shared(smc);          // A bufs
    uint32_t sB0 = sA0 + 32768;                                      // B bufs

    const int tid  = threadIdx.x;
    const int wid  = tid >> 5, lane = tid & 31;
    const int gid  = lane >> 2, tg = lane & 3;
    const int l8   = lane & 7,  sub = lane >> 3;
    const int m0   = blockIdx.y * 128, n0 = blockIdx.x * 128;
    const int wm   = (wid >> 2) * 64;
    const int wn   = (wid & 3) * 32;

    float acc[4][4][4];
#pragma unroll
    for (int mi = 0; mi < 4; mi++)
#pragma unroll
        for (int ni = 0; ni < 4; ni++)
#pragma unroll
            for (int r = 0; r < 4; r++) acc[mi][ni][r] = 0.0f;

    const int NC = K >> 6;   // 64-half chunks

    // Per-chunk tile loader: 128 rows x 64 halves (128B rows, 8x16B chunks,
    // XOR-swizzled chunk ^ (row&7)); 4 cp16 per thread per matrix.
    auto loadTiles = [&](int buf, int kc) {
#pragma unroll
        for (int l = 0; l < 4; l++) {
            int idx = tid + l * 256;
            int row = idx >> 3, c = idx & 7;
            uint32_t d = sA0 + (uint32_t)(buf * 16384 + row * 128 + ((c ^ (row & 7)) << 4));
            cp16(d, A + (size_t)(m0 + row) * K + kc + c * 8);
        }
#pragma unroll
        for (int l = 0; l < 4; l++) {
            int idx = tid + l * 256;
            int row = idx >> 3, c = idx & 7;
            int j = n0 + row;
            int wr = PERM ? ((j & 511) * 3 + (j >> 9)) : j;
            uint32_t d = sB0 + (uint32_t)(buf * 16384 + row * 128 + ((c ^ (row & 7)) << 4));
            cp16(d, Wt + (size_t)wr * K + kc + c * 8);
        }
    };

    loadTiles(0, 0);
    asm volatile("cp.async.commit_group;");

    for (int c = 0; c < NC; c++) {
        if (c + 1 < NC) {
            loadTiles((c + 1) & 1, (c + 1) << 6);
            asm volatile("cp.async.commit_group;");
            asm volatile("cp.async.wait_group 1;" ::: "memory");
        } else {
            asm volatile("cp.async.wait_group 0;" ::: "memory");
        }
        __syncthreads();

        uint32_t aB = sA0 + (c & 1) * 16384;
        uint32_t bB = sB0 + (c & 1) * 16384;
#pragma unroll
        for (int ks = 0; ks < 4; ks++) {
            uint32_t a[4][4], b[2][4];
            // A: mat0 rows0-7/c0, mat1 rows8-15/c0, mat2 rows0-7/c0+1, mat3 rows8-15/c0+1
            int cA = (2 * ks + (sub >> 1)) ^ l8;
#pragma unroll
            for (int mi = 0; mi < 4; mi++) {
                int row = wm + mi * 16 + ((sub & 1) << 3) + l8;
                LDSM_X4(a[mi], aB + (uint32_t)(row * 128 + (cA << 4)));
            }
            // B: mat0 rows0-7/c0, mat1 rows0-7/c0+1, mat2 rows8-15/c0, mat3 rows8-15/c0+1
            int cB = (2 * ks + (sub & 1)) ^ l8;
#pragma unroll
            for (int nq = 0; nq < 2; nq++) {
                int row = wn + nq * 16 + ((sub >> 1) << 3) + l8;
                LDSM_X4(b[nq], bB + (uint32_t)(row * 128 + (cB << 4)));
            }
#pragma unroll
            for (int mi = 0; mi < 4; mi++)
#pragma unroll
                for (int ni = 0; ni < 4; ni++)
                    mma16816(acc[mi][ni], a[mi], &b[ni >> 1][(ni & 1) * 2]);
        }
        __syncthreads();
    }

    // Epilogue: c0,c1 -> (row gid, col 2tg..); c2,c3 -> (row gid+8, ...)
#pragma unroll
    for (int ni = 0; ni < 4; ni++) {
        int col = n0 + wn + ni * 8 + 2 * tg;
        float2 bv = make_float2(0.f, 0.f);
        if (HAS_BIAS) bv = *(const float2*)(bias + col);
#pragma unroll
        for (int mi = 0; mi < 4; mi++) {
            int row0 = m0 + wm + mi * 16 + gid;
#pragma unroll
            for (int h = 0; h < 2; h++) {
                int row = row0 + h * 8;
                float vx = acc[mi][ni][2 * h + 0];
                float vy = acc[mi][ni][2 * h + 1];
                if (HAS_BIAS) { vx += bv.x; vy += bv.y; }
                if (RELU) { vx = fmaxf(vx, 0.f); vy = fmaxf(vy, 0.f); }
                size_t off = (size_t)row * Nn + col;
                if (OUT_HALF) {
                    *(__half2*)((__half*)CdV + off) = __floats2half2_rn(vx, vy);
                } else {
                    float* Cd = (float*)CdV;
                    float2 o;
                    if (ACCUM) {
                        o = *(const float2*)(Cd + off);
                        o.x += vx; o.y += vy;
                    } else {
                        o = make_float2(vx, vy);
                    }
                    *(float2*)(Cd + off) = o;
                }
            }
        }
    }
}

// ---------------------------------------------------------------------------
// Axial attention; qkv/ctx are fp16, compute fp32
// ---------------------------------------------------------------------------
__device__ __forceinline__ float warpMaxf(float v) {
#pragma unroll
    for (int o = 16; o > 0; o >>= 1) v = fmaxf(v, __shfl_xor_sync(0xffffffffu, v, o));
    return v;
}
__device__ __forceinline__ float warpSumf(float v) {
#pragma unroll
    for (int o = 16; o > 0; o >>= 1) v += __shfl_xor_sync(0xffffffffu, v, o);
    return v;
}

template<int L, int QT, int JB, bool AXIS_H>
__global__ __launch_bounds__(256)
void attn_kernel(const __half* __restrict__ qkv, __half* __restrict__ ctx)
{
    constexpr int KC = 16;
    constexpr int II = QT / 16;
    constexpr int JJ = L / 16;
    constexpr int CCH = 64;
    constexpr int NJB = L / JB;

    __shared__ float S [QT][L + 1];
    __shared__ float Qs[KC][QT + 1];
    __shared__ float Ks[KC][L + 1];
    __shared__ float Vs[JB][CCH + 4];

    int tid = threadIdx.x;
    size_t base; int rstride;
    if (AXIS_H) {
        int b = blockIdx.y / WW, w = blockIdx.y % WW;
        base = (size_t)b * HH * WW + w; rstride = WW;
    } else {
        base = (size_t)blockIdx.y * WW; rstride = 1;
    }
    int q0 = blockIdx.x * QT;
    int ty = tid >> 4, tx = tid & 15;

    float acc[II][JJ];
#pragma unroll
    for (int i = 0; i < II; i++)
#pragma unroll
        for (int j = 0; j < JJ; j++) acc[i][j] = 0.0f;

    for (int kc = 0; kc < CH; kc += KC) {
        for (int idx = tid; idx < QT * KC; idx += 256) {
            int i = idx >> 4, k = idx & 15;
            Qs[k][i] = __half2float(qkv[(base + (size_t)(q0 + i) * rstride) * C3 + kc + k]);
        }
        for (int idx = tid; idx < L * KC; idx += 256) {
            int j = idx >> 4, k = idx & 15;
            Ks[k][j] = __half2float(qkv[(base + (size_t)j * rstride) * C3 + CH + kc + k]);
        }
        __syncthreads();
#pragma unroll
        for (int k = 0; k < KC; k++) {
            float av[II], kv[JJ];
#pragma unroll
            for (int i = 0; i < II; i++) av[i] = Qs[k][ty + 16 * i];
#pragma unroll
            for (int j = 0; j < JJ; j++) kv[j] = Ks[k][tx + 16 * j];
#pragma unroll
            for (int i = 0; i < II; i++)
#pragma unroll
                for (int j = 0; j < JJ; j++) acc[i][j] += av[i] * kv[j];
        }
        __syncthreads();
    }
    const float scale = 0.04419417382415922f;  // 1/sqrt(512)
#pragma unroll
    for (int i = 0; i < II; i++)
#pragma unroll
        for (int j = 0; j < JJ; j++) S[ty + 16 * i][tx + 16 * j] = acc[i][j] * scale;
    __syncthreads();

    int warp = tid >> 5, lane = tid & 31;
    for (int r = warp; r < QT; r += 8) {
        float mx = -1e30f;
        for (int j = lane; j < L; j += 32) mx = fmaxf(mx, S[r][j]);
        mx = warpMaxf(mx);
        float sm = 0.0f;
        for (int j = lane; j < L; j += 32) {
            float e = __expf(S[r][j] - mx);
            S[r][j] = e; sm += e;
        }
        sm = warpSumf(sm);
        float inv = 1.0f / sm;
        for (int j = lane; j < L; j += 32) S[r][j] *= inv;
    }
    __syncthreads();

    for (int c0 = 0; c0 < CH; c0 += CCH) {
        float acc2[II][4];
#pragma unroll
        for (int i = 0; i < II; i++)
#pragma unroll
            for (int u = 0; u < 4; u++) acc2[i][u] = 0.0f;

        for (int jb = 0; jb < NJB; jb++) {
            for (int idx = tid; idx < JB * CCH; idx += 256) {
                int j = idx >> 6, cl = idx & 63;
                Vs[j][cl] = __half2float(
                    qkv[(base + (size_t)(jb * JB + j) * rstride) * C3 + 2 * CH + c0 + cl]);
            }
            __syncthreads();
#pragma unroll 4
            for (int j = 0; j < JB; j++) {
                float pv[II];
#pragma unroll
                for (int i = 0; i < II; i++) pv[i] = S[ty + 16 * i][jb * JB + j];
                float4 vv = *(const float4*)&Vs[j][tx * 4];
#pragma unroll
                for (int i = 0; i < II; i++) {
                    acc2[i][0] += pv[i] * vv.x;
                    acc2[i][1] += pv[i] * vv.y;
                    acc2[i][2] += pv[i] * vv.z;
                    acc2[i][3] += pv[i] * vv.w;
                }
            }
            __syncthreads();
        }
#pragma unroll
        for (int i = 0; i < II; i++) {
            int qi = ty + 16 * i;
            size_t t = base + (size_t)(q0 + qi) * rstride;
            __half2 h0 = __floats2half2_rn(acc2[i][0], acc2[i][1]);
            __half2 h1 = __floats2half2_rn(acc2[i][2], acc2[i][3]);
            __half2* dst = (__half2*)&ctx[t * CH + c0 + tx * 4];
            dst[0] = h0; dst[1] = h1;
        }
    }
}

// ---------------------------------------------------------------------------
// Launch
// ---------------------------------------------------------------------------
extern "C" void kernel_launch(void* const* d_in, const int* in_sizes, int n_in,
                              void* d_out, int out_size)
{
    const float* x      = (const float*)d_in[0];
    const float* w_qkv1 = (const float*)d_in[1];
    const float* w_out1 = (const float*)d_in[2];
    const float* w_qkv2 = (const float*)d_in[3];
    const float* w_out2 = (const float*)d_in[4];
    const float* g1 = (const float*)d_in[5],  *b1 = (const float*)d_in[6];
    const float* g2 = (const float*)d_in[7],  *b2 = (const float*)d_in[8];
    const float* g3 = (const float*)d_in[9],  *b3 = (const float*)d_in[10];
    const float* w_fc1 = (const float*)d_in[11], *b_fc1 = (const float*)d_in[12];
    const float* w_fc2 = (const float*)d_in[13], *b_fc2 = (const float*)d_in[14];
    float* out = (float*)d_out;

    float *X; __half *LN, *QKV, *CTX, *Hb, *WR;
    cudaGetSymbolAddress((void**)&X,   g_x);
    cudaGetSymbolAddress((void**)&LN,  g_ln);
    cudaGetSymbolAddress((void**)&QKV, g_qkv);
    cudaGetSymbolAddress((void**)&CTX, g_ctx);
    cudaGetSymbolAddress((void**)&Hb,  g_h);
    cudaGetSymbolAddress((void**)&WR,  g_wr);

    cudaFuncSetAttribute(mma_gemm<true,  false, false, false, true >,
                         cudaFuncAttributeMaxDynamicSharedMemorySize, GEMM_SMEM);
    cudaFuncSetAttribute(mma_gemm<false, false, false, true,  false>,
                         cudaFuncAttributeMaxDynamicSharedMemorySize, GEMM_SMEM);
    cudaFuncSetAttribute(mma_gemm<false, true,  true,  false, true >,
                         cudaFuncAttributeMaxDynamicSharedMemorySize, GEMM_SMEM);
    cudaFuncSetAttribute(mma_gemm<false, true,  false, true,  false>,
                         cudaFuncAttributeMaxDynamicSharedMemorySize, GEMM_SMEM);

    // fp16 weight conversion (graph-capturable kernels)
    f2h_kernel<<<(C3*CH/4 + 255)/256, 256>>>(w_qkv1, WR + O_WQ1, C3*CH/4);
    f2h_kernel<<<(CH*CH/4 + 255)/256, 256>>>(w_out1, WR + O_WO1, CH*CH/4);
    f2h_kernel<<<(C3*CH/4 + 255)/256, 256>>>(w_qkv2, WR + O_WQ2, C3*CH/4);
    f2h_kernel<<<(CH*CH/4 + 255)/256, 256>>>(w_out2, WR + O_WO2, CH*CH/4);
    f2h_kernel<<<(C4*CH/4 + 255)/256, 256>>>(w_fc1,  WR + O_FC1, C4*CH/4);
    f2h_kernel<<<(CH*C4/4 + 255)/256, 256>>>(w_fc2,  WR + O_FC2, CH*C4/4);

    dim3 tb(32, 8);
    dim3 tgrid(WW / 32, CH / 32, NB * HH);

    transpose_in_kernel<<<tgrid, tb>>>(x, X);

    // Block 1: attention along H
    ln_kernel<<<NTOK, 128>>>(X, LN, g1, b1);
    mma_gemm<true,  false, false, false, true ><<<dim3(C3 / 128, NTOK / 128), 256, GEMM_SMEM>>>(LN, WR + O_WQ1, nullptr, QKV, NTOK, C3, CH);
    attn_kernel<48, 48, 48, true><<<dim3(1, NB * WW), 256>>>(QKV, CTX);
    mma_gemm<false, false, false, true,  false><<<dim3(CH / 128, NTOK / 128), 256, GEMM_SMEM>>>(CTX, WR + O_WO1, nullptr, X, NTOK, CH, CH);

    // Block 2: attention along W
    ln_kernel<<<NTOK, 128>>>(X, LN, g2, b2);
    mma_gemm<true,  false, false, false, true ><<<dim3(C3 / 128, NTOK / 128), 256, GEMM_SMEM>>>(LN, WR + O_WQ2, nullptr, QKV, NTOK, C3, CH);
    attn_kernel<192, 32, 32, false><<<dim3(192 / 32, NB * HH), 256>>>(QKV, CTX);
    mma_gemm<false, false, false, true,  false><<<dim3(CH / 128, NTOK / 128), 256, GEMM_SMEM>>>(CTX, WR + O_WO2, nullptr, X, NTOK, CH, CH);

    // MLP
    ln_kernel<<<NTOK, 128>>>(X, LN, g3, b3);
    mma_gemm<false, true,  true,  false, true ><<<dim3(C4 / 128, NTOK / 128), 256, GEMM_SMEM>>>(LN, WR + O_FC1, b_fc1, Hb, NTOK, C4, CH);
    mma_gemm<false, true,  false, true,  false><<<dim3(CH / 128, NTOK / 128), 256, GEMM_SMEM>>>(Hb, WR + O_FC2, b_fc2, X, NTOK, CH, C4);

    transpose_out_kernel<<<tgrid, tb>>>(X, out);
}

// round 10
// speedup vs baseline: 7.6943x; 1.6803x over previous
#include <cuda_runtime.h>
#include <cuda_fp16.h>
#include <math.h>
#include <stdint.h>

// Problem constants
#define NB 8
#define CH 512
#define HH 48
#define WW 192
#define NTOK (NB*HH*WW)      // 73728 tokens
#define C3 (3*CH)            // 1536
#define C4 (4*CH)            // 2048

// Scratch (static device allocations)
__device__ float  g_x  [(size_t)NTOK * CH];   // residual stream (fp32)
__device__ __half g_ln [(size_t)NTOK * CH];   // layernorm output
__device__ __half g_qkv[(size_t)NTOK * C3];   // de-interleaved [q|k|v]
__device__ __half g_ctx[(size_t)NTOK * CH];   // attention context
__device__ __half g_h  [(size_t)NTOK * C4];   // MLP hidden
__device__ __half g_wr [4194304];             // fp16 weights

#define O_WQ1 0
#define O_WO1 786432
#define O_WQ2 1048576
#define O_WO2 1835008
#define O_FC1 2097152
#define O_FC2 3145728

// ---------------------------------------------------------------------------
// fp32 -> fp16 weight conversion
// ---------------------------------------------------------------------------
__global__ void f2h_kernel(const float* __restrict__ in, __half* __restrict__ out, int n4)
{
    int i = blockIdx.x * blockDim.x + threadIdx.x;
    if (i < n4) {
        float4 v = ((const float4*)in)[i];
        ((__half2*)out)[2 * i]     = __floats2half2_rn(v.x, v.y);
        ((__half2*)out)[2 * i + 1] = __floats2half2_rn(v.z, v.w);
    }
}

// ---------------------------------------------------------------------------
// Transposes
// ---------------------------------------------------------------------------
__global__ void transpose_in_kernel(const float* __restrict__ x, float* __restrict__ X)
{
    __shared__ float tile[32][33];
    int bh = blockIdx.z; int b = bh / HH, h = bh % HH;
    int w0 = blockIdx.x * 32, c0 = blockIdx.y * 32;
#pragma unroll
    for (int r = 0; r < 4; r++) {
        int c = c0 + threadIdx.y + r * 8;
        tile[threadIdx.y + r * 8][threadIdx.x] =
            x[(((size_t)b * CH + c) * HH + h) * WW + w0 + threadIdx.x];
    }
    __syncthreads();
#pragma unroll
    for (int r = 0; r < 4; r++) {
        int w = w0 + threadIdx.y + r * 8;
        X[(((size_t)b * HH + h) * WW + w) * CH + c0 + threadIdx.x] =
            tile[threadIdx.x][threadIdx.y + r * 8];
    }
}

__global__ void transpose_out_kernel(const float* __restrict__ X, float* __restrict__ out)
{
    __shared__ float tile[32][33];
    int bh = blockIdx.z; int b = bh / HH, h = bh % HH;
    int w0 = blockIdx.x * 32, c0 = blockIdx.y * 32;
#pragma unroll
    for (int r = 0; r < 4; r++) {
        int w = w0 + threadIdx.y + r * 8;
        tile[threadIdx.y + r * 8][threadIdx.x] =
            X[(((size_t)b * HH + h) * WW + w) * CH + c0 + threadIdx.x];
    }
    __syncthreads();
#pragma unroll
    for (int r = 0; r < 4; r++) {
        int c = c0 + threadIdx.y + r * 8;
        out[(((size_t)b * CH + c) * HH + h) * WW + w0 + threadIdx.x] =
            tile[threadIdx.x][threadIdx.y + r * 8];
    }
}

// ---------------------------------------------------------------------------
// Row LayerNorm (C=512); fp32 in, fp16 out (feeds GEMMs only)
// ---------------------------------------------------------------------------
__global__ void ln_kernel(const float* __restrict__ X, __half* __restrict__ Y,
                          const float* __restrict__ g, const float* __restrict__ b)
{
    __shared__ float red[8];
    size_t t = blockIdx.x;
    float4 v = ((const float4*)(X + t * CH))[threadIdx.x];
    float s = v.x + v.y + v.z + v.w;
    float q = v.x * v.x + v.y * v.y + v.z * v.z + v.w * v.w;
#pragma unroll
    for (int o = 16; o > 0; o >>= 1) {
        s += __shfl_xor_sync(0xffffffffu, s, o);
        q += __shfl_xor_sync(0xffffffffu, q, o);
    }
    int warp = threadIdx.x >> 5;
    if ((threadIdx.x & 31) == 0) { red[warp] = s; red[warp + 4] = q; }
    __syncthreads();
    s = red[0] + red[1] + red[2] + red[3];
    q = red[4] + red[5] + red[6] + red[7];
    float mean = s * (1.0f / CH);
    float var  = q * (1.0f / CH) - mean * mean;
    float rs = rsqrtf(var + 1e-5f);
    float4 gg = ((const float4*)g)[threadIdx.x];
    float4 bb = ((const float4*)b)[threadIdx.x];
    __half2* Yp = (__half2*)(Y + t * CH);
    Yp[2 * threadIdx.x]     = __floats2half2_rn((v.x - mean) * rs * gg.x + bb.x,
                                                (v.y - mean) * rs * gg.y + bb.y);
    Yp[2 * threadIdx.x + 1] = __floats2half2_rn((v.z - mean) * rs * gg.z + bb.z,
                                                (v.w - mean) * rs * gg.w + bb.w);
}

// ---------------------------------------------------------------------------
// Shared mma helpers
// ---------------------------------------------------------------------------
__device__ __forceinline__ void cp16(uint32_t dst, const void* src) {
    asm volatile("cp.async.cg.shared.global [%0], [%1], 16;" :: "r"(dst), "l"(src));
}

#define LDSM_X4(R, addr) \
    asm volatile("ldmatrix.sync.aligned.m8n8.x4.shared.b16 {%0,%1,%2,%3}, [%4];" \
                 : "=r"((R)[0]), "=r"((R)[1]), "=r"((R)[2]), "=r"((R)[3]) : "r"(addr))

#define LDSM_X4_T(R, addr) \
    asm volatile("ldmatrix.sync.aligned.m8n8.x4.trans.shared.b16 {%0,%1,%2,%3}, [%4];" \
                 : "=r"((R)[0]), "=r"((R)[1]), "=r"((R)[2]), "=r"((R)[3]) : "r"(addr))

__device__ __forceinline__ void mma16816(float* c, const uint32_t* a, const uint32_t* b) {
    asm volatile(
        "mma.sync.aligned.m16n8k16.row.col.f32.f16.f16.f32 "
        "{%0,%1,%2,%3}, {%4,%5,%6,%7}, {%8,%9}, {%0,%1,%2,%3};"
        : "+f"(c[0]), "+f"(c[1]), "+f"(c[2]), "+f"(c[3])
        : "r"(a[0]), "r"(a[1]), "r"(a[2]), "r"(a[3]), "r"(b[0]), "r"(b[1]));
}

__device__ __forceinline__ float warpMaxf(float v) {
#pragma unroll
    for (int o = 16; o > 0; o >>= 1) v = fmaxf(v, __shfl_xor_sync(0xffffffffu, v, o));
    return v;
}
__device__ __forceinline__ float warpSumf(float v) {
#pragma unroll
    for (int o = 16; o > 0; o >>= 1) v += __shfl_xor_sync(0xffffffffu, v, o);
    return v;
}

// ---------------------------------------------------------------------------
// fp16 mma.sync GEMM: C[M,Nn] = A[M,K] @ W[Nn,K]^T (NT, K-contiguous halves)
// ---------------------------------------------------------------------------
#define GEMM_SMEM 65536   // A[2]:32KB + B[2]:32KB (128 rows x 128B each)

template<bool PERM, bool HAS_BIAS, bool RELU, bool ACCUM, bool OUT_HALF>
__global__ __launch_bounds__(256, 2)
void mma_gemm(const __half* __restrict__ A, const __half* __restrict__ Wt,
              const float* __restrict__ bias, void* __restrict__ CdV,
              int M, int Nn, int K)
{
    extern __shared__ char smc[];
    uint32_t sA0 = (uint32_t)__cvta_generic_to_shared(smc);
    uint32_t sB0 = sA0 + 32768;

    const int tid  = threadIdx.x;
    const int wid  = tid >> 5, lane = tid & 31;
    const int gid  = lane >> 2, tg = lane & 3;
    const int l8   = lane & 7,  sub = lane >> 3;
    const int m0   = blockIdx.y * 128, n0 = blockIdx.x * 128;
    const int wm   = (wid >> 2) * 64;
    const int wn   = (wid & 3) * 32;

    float acc[4][4][4];
#pragma unroll
    for (int mi = 0; mi < 4; mi++)
#pragma unroll
        for (int ni = 0; ni < 4; ni++)
#pragma unroll
            for (int r = 0; r < 4; r++) acc[mi][ni][r] = 0.0f;

    const int NC = K >> 6;

    auto loadTiles = [&](int buf, int kc) {
#pragma unroll
        for (int l = 0; l < 4; l++) {
            int idx = tid + l * 256;
            int row = idx >> 3, c = idx & 7;
            uint32_t d = sA0 + (uint32_t)(buf * 16384 + row * 128 + ((c ^ (row & 7)) << 4));
            cp16(d, A + (size_t)(m0 + row) * K + kc + c * 8);
        }
#pragma unroll
        for (int l = 0; l < 4; l++) {
            int idx = tid + l * 256;
            int row = idx >> 3, c = idx & 7;
            int j = n0 + row;
            int wr = PERM ? ((j & 511) * 3 + (j >> 9)) : j;
            uint32_t d = sB0 + (uint32_t)(buf * 16384 + row * 128 + ((c ^ (row & 7)) << 4));
            cp16(d, Wt + (size_t)wr * K + kc + c * 8);
        }
    };

    loadTiles(0, 0);
    asm volatile("cp.async.commit_group;");

    for (int c = 0; c < NC; c++) {
        if (c + 1 < NC) {
            loadTiles((c + 1) & 1, (c + 1) << 6);
            asm volatile("cp.async.commit_group;");
            asm volatile("cp.async.wait_group 1;" ::: "memory");
        } else {
            asm volatile("cp.async.wait_group 0;" ::: "memory");
        }
        __syncthreads();

        uint32_t aB = sA0 + (c & 1) * 16384;
        uint32_t bB = sB0 + (c & 1) * 16384;
#pragma unroll
        for (int ks = 0; ks < 4; ks++) {
            uint32_t a[4][4], b[2][4];
            int cA = (2 * ks + (sub >> 1)) ^ l8;
#pragma unroll
            for (int mi = 0; mi < 4; mi++) {
                int row = wm + mi * 16 + ((sub & 1) << 3) + l8;
                LDSM_X4(a[mi], aB + (uint32_t)(row * 128 + (cA << 4)));
            }
            int cB = (2 * ks + (sub & 1)) ^ l8;
#pragma unroll
            for (int nq = 0; nq < 2; nq++) {
                int row = wn + nq * 16 + ((sub >> 1) << 3) + l8;
                LDSM_X4(b[nq], bB + (uint32_t)(row * 128 + (cB << 4)));
            }
#pragma unroll
            for (int mi = 0; mi < 4; mi++)
#pragma unroll
                for (int ni = 0; ni < 4; ni++)
                    mma16816(acc[mi][ni], a[mi], &b[ni >> 1][(ni & 1) * 2]);
        }
        __syncthreads();
    }

#pragma unroll
    for (int ni = 0; ni < 4; ni++) {
        int col = n0 + wn + ni * 8 + 2 * tg;
        float2 bv = make_float2(0.f, 0.f);
        if (HAS_BIAS) bv = *(const float2*)(bias + col);
#pragma unroll
        for (int mi = 0; mi < 4; mi++) {
            int row0 = m0 + wm + mi * 16 + gid;
#pragma unroll
            for (int h = 0; h < 2; h++) {
                int row = row0 + h * 8;
                float vx = acc[mi][ni][2 * h + 0];
                float vy = acc[mi][ni][2 * h + 1];
                if (HAS_BIAS) { vx += bv.x; vy += bv.y; }
                if (RELU) { vx = fmaxf(vx, 0.f); vy = fmaxf(vy, 0.f); }
                size_t off = (size_t)row * Nn + col;
                if (OUT_HALF) {
                    *(__half2*)((__half*)CdV + off) = __floats2half2_rn(vx, vy);
                } else {
                    float* Cd = (float*)CdV;
                    float2 o;
                    if (ACCUM) {
                        o = *(const float2*)(Cd + off);
                        o.x += vx; o.y += vy;
                    } else {
                        o = make_float2(vx, vy);
                    }
                    *(float2*)(Cd + off) = o;
                }
            }
        }
    }
}

// ---------------------------------------------------------------------------
// W-axis attention (L=192), tensor-core flash-style.
// 2 CTAs per (b,h), 96 queries each, 256 threads / 8 warps.
// Pass1: S = QK^T (fp16 S, pitch 400B). Softmax fp32 in-place. Pass2: P@V.
// ---------------------------------------------------------------------------
#define WSM_Q 0
#define WSM_K 12288
#define WSM_S 36864        // 96 rows x 400B = 38400
#define WSM_TOTAL 75264
#define SCALE_ATTN 0.04419417382415922f  // 1/sqrt(512)

__global__ __launch_bounds__(256, 2)
void attn_w_mma(const __half* __restrict__ qkv, __half* __restrict__ ctx)
{
    extern __shared__ char wsm[];
    uint32_t sb = (uint32_t)__cvta_generic_to_shared(wsm);
    const uint32_t sQ = sb + WSM_Q, sK = sb + WSM_K, sS = sb + WSM_S, sV = sb;

    const int tid = threadIdx.x;
    const int wid = tid >> 5, lane = tid & 31;
    const int gid = lane >> 2, tg = lane & 3;
    const int l8  = lane & 7,  sub = lane >> 3;
    const size_t base = (size_t)blockIdx.y * WW;
    const int q0 = blockIdx.x * 96;
    const int wm = (wid >> 2) * 48;       // {0,48}
    const int wn = (wid & 3) * 48;        // {0,48,96,144}

    float acc[3][6][4];
#pragma unroll
    for (int mi = 0; mi < 3; mi++)
#pragma unroll
        for (int ni = 0; ni < 6; ni++)
#pragma unroll
            for (int r = 0; r < 4; r++) acc[mi][ni][r] = 0.0f;

    // ---- Pass 1: S = Q K^T over kc chunks of 64 ----
    for (int kc = 0; kc < CH; kc += 64) {
#pragma unroll
        for (int l = 0; l < 3; l++) {                 // Q: 96 rows x 8 chunks
            int idx = tid + l * 256;
            int row = idx >> 3, c = idx & 7;
            cp16(sQ + (uint32_t)(row * 128 + ((c ^ (row & 7)) << 4)),
                 qkv + (base + q0 + row) * C3 + kc + c * 8);
        }
#pragma unroll
        for (int l = 0; l < 6; l++) {                 // K: 192 rows x 8 chunks
            int idx = tid + l * 256;
            int row = idx >> 3, c = idx & 7;
            cp16(sK + (uint32_t)(row * 128 + ((c ^ (row & 7)) << 4)),
                 qkv + (base + row) * C3 + CH + kc + c * 8);
        }
        asm volatile("cp.async.commit_group;");
        asm volatile("cp.async.wait_group 0;" ::: "memory");
        __syncthreads();
#pragma unroll
        for (int ks = 0; ks < 4; ks++) {
            uint32_t a[3][4], b[3][4];
            int cA = (2 * ks + (sub >> 1)) ^ l8;
#pragma unroll
            for (int mi = 0; mi < 3; mi++) {
                int row = wm + mi * 16 + ((sub & 1) << 3) + l8;
                LDSM_X4(a[mi], sQ + (uint32_t)(row * 128 + (cA << 4)));
            }
            int cB = (2 * ks + (sub & 1)) ^ l8;
#pragma unroll
            for (int nq = 0; nq < 3; nq++) {
                int row = wn + nq * 16 + ((sub >> 1) << 3) + l8;
                LDSM_X4(b[nq], sK + (uint32_t)(row * 128 + (cB << 4)));
            }
#pragma unroll
            for (int mi = 0; mi < 3; mi++)
#pragma unroll
                for (int ni = 0; ni < 6; ni++)
                    mma16816(acc[mi][ni], a[mi], &b[ni >> 1][(ni & 1) * 2]);
        }
        __syncthreads();
    }
    // write S (fp16, pitch 400B)
#pragma unroll
    for (int mi = 0; mi < 3; mi++)
#pragma unroll
        for (int ni = 0; ni < 6; ni++) {
            int row = wm + mi * 16 + gid;
            int col = wn + ni * 8 + 2 * tg;
            *(__half2*)(wsm + WSM_S + (size_t)row * 400 + col * 2) =
                __floats2half2_rn(acc[mi][ni][0] * SCALE_ATTN, acc[mi][ni][1] * SCALE_ATTN);
            *(__half2*)(wsm + WSM_S + (size_t)(row + 8) * 400 + col * 2) =
                __floats2half2_rn(acc[mi][ni][2] * SCALE_ATTN, acc[mi][ni][3] * SCALE_ATTN);
        }
    __syncthreads();

    // ---- Softmax (fp32 math, fp16 in place) ----
    for (int r = wid; r < 96; r += 8) {
        __half* Srow = (__half*)(wsm + WSM_S + (size_t)r * 400);
        float mx = -1e30f;
#pragma unroll
        for (int it = 0; it < 6; it++) mx = fmaxf(mx, __half2float(Srow[lane + it * 32]));
        mx = warpMaxf(mx);
        float e[6], sm = 0.0f;
#pragma unroll
        for (int it = 0; it < 6; it++) {
            e[it] = __expf(__half2float(Srow[lane + it * 32]) - mx);
            sm += e[it];
        }
        sm = warpSumf(sm);
        float inv = 1.0f / sm;
#pragma unroll
        for (int it = 0; it < 6; it++) Srow[lane + it * 32] = __float2half(e[it] * inv);
    }
    __syncthreads();

    // ---- Pass 2: ctx = P @ V, 64 ctx cols per pass (V aliases Q/K region) ----
    const int wn2 = (wid & 3) * 16;
    for (int c0 = 0; c0 < CH; c0 += 64) {
#pragma unroll
        for (int l = 0; l < 6; l++) {                 // V: 192 rows x 8 chunks
            int idx = tid + l * 256;
            int row = idx >> 3, c = idx & 7;
            cp16(sV + (uint32_t)(row * 128 + ((c ^ (row & 7)) << 4)),
                 qkv + (base + row) * C3 + 2 * CH + c0 + c * 8);
        }
        asm volatile("cp.async.commit_group;");
        asm volatile("cp.async.wait_group 0;" ::: "memory");
        __syncthreads();

        float acc2[3][2][4];
#pragma unroll
        for (int mi = 0; mi < 3; mi++)
#pragma unroll
            for (int ni = 0; ni < 2; ni++)
#pragma unroll
                for (int r = 0; r < 4; r++) acc2[mi][ni][r] = 0.0f;

#pragma unroll 4
        for (int kb = 0; kb < 12; kb++) {
            uint32_t a[3][4], v[4];
            int cA = 2 * kb + (sub >> 1);             // P: no swizzle (pitch 400)
#pragma unroll
            for (int mi = 0; mi < 3; mi++) {
                int row = wm + mi * 16 + ((sub & 1) << 3) + l8;
                LDSM_X4(a[mi], sS + (uint32_t)(row * 400 + (cA << 4)));
            }
            int rowv = kb * 16 + ((sub & 1) << 3) + l8;
            int cV = ((wn2 >> 3) + (sub >> 1)) ^ l8;
            LDSM_X4_T(v, sV + (uint32_t)(rowv * 128 + (cV << 4)));
#pragma unroll
            for (int mi = 0; mi < 3; mi++)
#pragma unroll
                for (int ni = 0; ni < 2; ni++)
                    mma16816(acc2[mi][ni], a[mi], &v[ni * 2]);
        }
        __syncthreads();
#pragma unroll
        for (int mi = 0; mi < 3; mi++)
#pragma unroll
            for (int ni = 0; ni < 2; ni++) {
                int row = wm + mi * 16 + gid;
                int col = c0 + wn2 + ni * 8 + 2 * tg;
                size_t t0 = base + q0 + row;
                *(__half2*)&ctx[t0 * CH + col] =
                    __floats2half2_rn(acc2[mi][ni][0], acc2[mi][ni][1]);
                *(__half2*)&ctx[(t0 + 8) * CH + col] =
                    __floats2half2_rn(acc2[mi][ni][2], acc2[mi][ni][3]);
            }
    }
}

// ---------------------------------------------------------------------------
// H-axis attention (L=48), tensor-core. One CTA per (b,w), 128 thr / 4 warps.
// K/V padded to 64 rows (pad rows zeroed once). S fp16 swizzled 128B rows.
// ---------------------------------------------------------------------------
__global__ __launch_bounds__(128)
void attn_h_mma(const __half* __restrict__ qkv, __half* __restrict__ ctx)
{
    __shared__ __align__(16) char hsm[28672];
    // Q: 0..6144 (48x128B), K: 6144..14336 (64x128B),
    // S: 14336..20480 (48x128B), V: 20480..28672 (64x128B)
    uint32_t sb = (uint32_t)__cvta_generic_to_shared(hsm);
    const uint32_t sQ = sb, sK = sb + 6144, sS = sb + 14336, sV = sb + 20480;

    const int tid = threadIdx.x;
    const int wid = tid >> 5, lane = tid & 31;
    const int gid = lane >> 2, tg = lane & 3;
    const int l8  = lane & 7,  sub = lane >> 3;
    const int b   = blockIdx.x / WW, w = blockIdx.x % WW;
    const size_t base = (size_t)b * HH * WW + w;
    const int wn = wid * 16;

    // zero pad rows 48-63 of K and V (never overwritten by loads)
    {
        uint4 z = make_uint4(0, 0, 0, 0);
        ((uint4*)(hsm + 6144 + 48 * 128))[tid]  = z;   // 2048B = 128 x 16B
        ((uint4*)(hsm + 20480 + 48 * 128))[tid] = z;
    }

    float acc[3][2][4];
#pragma unroll
    for (int mi = 0; mi < 3; mi++)
#pragma unroll
        for (int ni = 0; ni < 2; ni++)
#pragma unroll
            for (int r = 0; r < 4; r++) acc[mi][ni][r] = 0.0f;

    // ---- Pass 1 ----
    for (int kc = 0; kc < CH; kc += 64) {
#pragma unroll
        for (int l = 0; l < 3; l++) {                 // Q: 48 rows x 8 chunks
            int idx = tid + l * 128;
            int row = idx >> 3, c = idx & 7;
            cp16(sQ + (uint32_t)(row * 128 + ((c ^ (row & 7)) << 4)),
                 qkv + (base + (size_t)row * WW) * C3 + kc + c * 8);
        }
#pragma unroll
        for (int l = 0; l < 3; l++) {                 // K: 48 rows x 8 chunks
            int idx = tid + l * 128;
            int row = idx >> 3, c = idx & 7;
            cp16(sK + (uint32_t)(row * 128 + ((c ^ (row & 7)) << 4)),
                 qkv + (base + (size_t)row * WW) * C3 + CH + kc + c * 8);
        }
        asm volatile("cp.async.commit_group;");
        asm volatile("cp.async.wait_group 0;" ::: "memory");
        __syncthreads();
#pragma unroll
        for (int ks = 0; ks < 4; ks++) {
            uint32_t a[3][4], bfr[4];
            int cA = (2 * ks + (sub >> 1)) ^ l8;
#pragma unroll
            for (int mi = 0; mi < 3; mi++) {
                int row = mi * 16 + ((sub & 1) << 3) + l8;
                LDSM_X4(a[mi], sQ + (uint32_t)(row * 128 + (cA << 4)));
            }
            int cB = (2 * ks + (sub & 1)) ^ l8;
            int rowb = wn + ((sub >> 1) << 3) + l8;
            LDSM_X4(bfr, sK + (uint32_t)(rowb * 128 + (cB << 4)));
#pragma unroll
            for (int mi = 0; mi < 3; mi++)
#pragma unroll
                for (int ni = 0; ni < 2; ni++)
                    mma16816(acc[mi][ni], a[mi], &bfr[ni * 2]);
        }
        __syncthreads();
    }
    // write S fp16 swizzled (cols 48-63 are zeros from zero-padded K)
#pragma unroll
    for (int mi = 0; mi < 3; mi++)
#pragma unroll
        for (int ni = 0; ni < 2; ni++) {
            int col = wn + ni * 8 + 2 * tg;
            int chunk = col >> 3, coff = (col & 7) * 2;
#pragma unroll
            for (int h = 0; h < 2; h++) {
                int row = mi * 16 + gid + h * 8;
                *(__half2*)(hsm + 14336 + row * 128 + ((chunk ^ (row & 7)) << 4) + coff) =
                    __floats2half2_rn(acc[mi][ni][2 * h] * SCALE_ATTN,
                                      acc[mi][ni][2 * h + 1] * SCALE_ATTN);
            }
        }
    __syncthreads();

    // ---- Softmax over j<48 (cols 48-63 stay exactly 0) ----
    for (int r = wid; r < 48; r += 4) {
        char* Sr = hsm + 14336 + r * 128;
        int s7 = r & 7;
        float mx = -1e30f, e0 = 0.f, e1 = 0.f;
        {
            int j = lane;
            mx = __half2float(*(__half*)(Sr + (((j >> 3) ^ s7) << 4) + (j & 7) * 2));
            if (lane < 16) {
                j = lane + 32;
                mx = fmaxf(mx, __half2float(*(__half*)(Sr + (((j >> 3) ^ s7) << 4) + (j & 7) * 2)));
            }
        }
        mx = warpMaxf(mx);
        {
            int j = lane;
            e0 = __expf(__half2float(*(__half*)(Sr + (((j >> 3) ^ s7) << 4) + (j & 7) * 2)) - mx);
            if (lane < 16) {
                j = lane + 32;
                e1 = __expf(__half2float(*(__half*)(Sr + (((j >> 3) ^ s7) << 4) + (j & 7) * 2)) - mx);
            }
        }
        float sm = warpSumf(e0 + e1);
        float inv = 1.0f / sm;
        {
            int j = lane;
            *(__half*)(Sr + (((j >> 3) ^ s7) << 4) + (j & 7) * 2) = __float2half(e0 * inv);
            if (lane < 16) {
                j = lane + 32;
                *(__half*)(Sr + (((j >> 3) ^ s7) << 4) + (j & 7) * 2) = __float2half(e1 * inv);
            }
        }
    }
    __syncthreads();

    // ---- Pass 2: ctx = P @ V over 64-col passes ----
    for (int c0 = 0; c0 < CH; c0 += 64) {
#pragma unroll
        for (int l = 0; l < 3; l++) {                 // V: 48 rows x 8 chunks
            int idx = tid + l * 128;
            int row = idx >> 3, c = idx & 7;
            cp16(sV + (uint32_t)(row * 128 + ((c ^ (row & 7)) << 4)),
                 qkv + (base + (size_t)row * WW) * C3 + 2 * CH + c0 + c * 8);
        }
        asm volatile("cp.async.commit_group;");
        asm volatile("cp.async.wait_group 0;" ::: "memory");
        __syncthreads();

        float acc2[3][2][4];
#pragma unroll
        for (int mi = 0; mi < 3; mi++)
#pragma unroll
            for (int ni = 0; ni < 2; ni++)
#pragma unroll
                for (int r = 0; r < 4; r++) acc2[mi][ni][r] = 0.0f;

#pragma unroll
        for (int kb = 0; kb < 4; kb++) {
            uint32_t a[3][4], v[4];
            int cA = (2 * kb + (sub >> 1)) ^ l8;      // S swizzled
#pragma unroll
            for (int mi = 0; mi < 3; mi++) {
                int row = mi * 16 + ((sub & 1) << 3) + l8;
                LDSM_X4(a[mi], sS + (uint32_t)(row * 128 + (cA << 4)));
            }
            int rowv = kb * 16 + ((sub & 1) << 3) + l8;
            int cV = ((wn >> 3) + (sub >> 1)) ^ l8;
            LDSM_X4_T(v, sV + (uint32_t)(rowv * 128 + (cV << 4)));
#pragma unroll
            for (int mi = 0; mi < 3; mi++)
#pragma unroll
                for (int ni = 0; ni < 2; ni++)
                    mma16816(acc2[mi][ni], a[mi], &v[ni * 2]);
        }
        __syncthreads();
#pragma unroll
        for (int mi = 0; mi < 3; mi++)
#pragma unroll
            for (int ni = 0; ni < 2; ni++) {
                int col = c0 + wn + ni * 8 + 2 * tg;
#pragma unroll
                for (int h = 0; h < 2; h++) {
                    int row = mi * 16 + gid + h * 8;
                    size_t t = base + (size_t)row * WW;
                    *(__half2*)&ctx[t * CH + col] =
                        __floats2half2_rn(acc2[mi][ni][2 * h], acc2[mi][ni][2 * h + 1]);
                }
            }
    }
}

// ---------------------------------------------------------------------------
// Launch
// ---------------------------------------------------------------------------
extern "C" void kernel_launch(void* const* d_in, const int* in_sizes, int n_in,
                              void* d_out, int out_size)
{
    const float* x      = (const float*)d_in[0];
    const float* w_qkv1 = (const float*)d_in[1];
    const float* w_out1 = (const float*)d_in[2];
    const float* w_qkv2 = (const float*)d_in[3];
    const float* w_out2 = (const float*)d_in[4];
    const float* g1 = (const float*)d_in[5],  *b1 = (const float*)d_in[6];
    const float* g2 = (const float*)d_in[7],  *b2 = (const float*)d_in[8];
    const float* g3 = (const float*)d_in[9],  *b3 = (const float*)d_in[10];
    const float* w_fc1 = (const float*)d_in[11], *b_fc1 = (const float*)d_in[12];
    const float* w_fc2 = (const float*)d_in[13], *b_fc2 = (const float*)d_in[14];
    float* out = (float*)d_out;

    float *X; __half *LN, *QKV, *CTX, *Hb, *WR;
    cudaGetSymbolAddress((void**)&X,   g_x);
    cudaGetSymbolAddress((void**)&LN,  g_ln);
    cudaGetSymbolAddress((void**)&QKV, g_qkv);
    cudaGetSymbolAddress((void**)&CTX, g_ctx);
    cudaGetSymbolAddress((void**)&Hb,  g_h);
    cudaGetSymbolAddress((void**)&WR,  g_wr);

    cudaFuncSetAttribute(mma_gemm<true,  false, false, false, true >,
                         cudaFuncAttributeMaxDynamicSharedMemorySize, GEMM_SMEM);
    cudaFuncSetAttribute(mma_gemm<false, false, false, true,  false>,
                         cudaFuncAttributeMaxDynamicSharedMemorySize, GEMM_SMEM);
    cudaFuncSetAttribute(mma_gemm<false, true,  true,  false, true >,
                         cudaFuncAttributeMaxDynamicSharedMemorySize, GEMM_SMEM);
    cudaFuncSetAttribute(mma_gemm<false, true,  false, true,  false>,
                         cudaFuncAttributeMaxDynamicSharedMemorySize, GEMM_SMEM);
    cudaFuncSetAttribute(attn_w_mma,
                         cudaFuncAttributeMaxDynamicSharedMemorySize, WSM_TOTAL);

    // fp16 weight conversion (graph-capturable kernels)
    f2h_kernel<<<(C3*CH/4 + 255)/256, 256>>>(w_qkv1, WR + O_WQ1, C3*CH/4);
    f2h_kernel<<<(CH*CH/4 + 255)/256, 256>>>(w_out1, WR + O_WO1, CH*CH/4);
    f2h_kernel<<<(C3*CH/4 + 255)/256, 256>>>(w_qkv2, WR + O_WQ2, C3*CH/4);
    f2h_kernel<<<(CH*CH/4 + 255)/256, 256>>>(w_out2, WR + O_WO2, CH*CH/4);
    f2h_kernel<<<(C4*CH/4 + 255)/256, 256>>>(w_fc1,  WR + O_FC1, C4*CH/4);
    f2h_kernel<<<(CH*C4/4 + 255)/256, 256>>>(w_fc2,  WR + O_FC2, CH*C4/4);

    dim3 tb(32, 8);
    dim3 tgrid(WW / 32, CH / 32, NB * HH);

    transpose_in_kernel<<<tgrid, tb>>>(x, X);

    // Block 1: attention along H
    ln_kernel<<<NTOK, 128>>>(X, LN, g1, b1);
    mma_gemm<true,  false, false, false, true ><<<dim3(C3 / 128, NTOK / 128), 256, GEMM_SMEM>>>(LN, WR + O_WQ1, nullptr, QKV, NTOK, C3, CH);
    attn_h_mma<<<NB * WW, 128>>>(QKV, CTX);
    mma_gemm<false, false, false, true,  false><<<dim3(CH / 128, NTOK / 128), 256, GEMM_SMEM>>>(CTX, WR + O_WO1, nullptr, X, NTOK, CH, CH);

    // Block 2: attention along W
    ln_kernel<<<NTOK, 128>>>(X, LN, g2, b2);
    mma_gemm<true,  false, false, false, true ><<<dim3(C3 / 128, NTOK / 128), 256, GEMM_SMEM>>>(LN, WR + O_WQ2, nullptr, QKV, NTOK, C3, CH);
    attn_w_mma<<<dim3(2, NB * HH), 256, WSM_TOTAL>>>(QKV, CTX);
    mma_gemm<false, false, false, true,  false><<<dim3(CH / 128, NTOK / 128), 256, GEMM_SMEM>>>(CTX, WR + O_WO2, nullptr, X, NTOK, CH, CH);

    // MLP
    ln_kernel<<<NTOK, 128>>>(X, LN, g3, b3);
    mma_gemm<false, true,  true,  false, true ><<<dim3(C4 / 128, NTOK / 128), 256, GEMM_SMEM>>>(LN, WR + O_FC1, b_fc1, Hb, NTOK, C4, CH);
    mma_gemm<false, true,  false, true,  false><<<dim3(CH / 128, NTOK / 128), 256, GEMM_SMEM>>>(Hb, WR + O_FC2, b_fc2, X, NTOK, CH, C4);

    transpose_out_kernel<<<tgrid, tb>>>(X, out);
}

// round 12
// speedup vs baseline: 7.7349x; 1.0053x over previous
#include <cuda_runtime.h>
#include <cuda_fp16.h>
#include <math.h>
#include <stdint.h>

// Problem constants
#define NB 8
#define CH 512
#define HH 48
#define WW 192
#define NTOK (NB*HH*WW)      // 73728 tokens
#define C3 (3*CH)            // 1536
#define C4 (4*CH)            // 2048

// Scratch (static device allocations)
__device__ float  g_x  [(size_t)NTOK * CH];   // residual stream (fp32)
__device__ __half g_ln [(size_t)NTOK * CH];   // layernorm output
__device__ __half g_qkv[(size_t)NTOK * C3];   // de-interleaved [q|k|v]
__device__ __half g_ctx[(size_t)NTOK * CH];   // attention context
__device__ __half g_h  [(size_t)NTOK * C4];   // MLP hidden
__device__ __half g_wr [4194304];             // fp16 weights

#define O_WQ1 0
#define O_WO1 786432
#define O_WQ2 1048576
#define O_WO2 1835008
#define O_FC1 2097152
#define O_FC2 3145728

// ---------------------------------------------------------------------------
// fp32 -> fp16 weight conversion
// ---------------------------------------------------------------------------
__global__ void f2h_kernel(const float* __restrict__ in, __half* __restrict__ out, int n4)
{
    int i = blockIdx.x * blockDim.x + threadIdx.x;
    if (i < n4) {
        float4 v = ((const float4*)in)[i];
        ((__half2*)out)[2 * i]     = __floats2half2_rn(v.x, v.y);
        ((__half2*)out)[2 * i + 1] = __floats2half2_rn(v.z, v.w);
    }
}

// ---------------------------------------------------------------------------
// Transposes
// ---------------------------------------------------------------------------
__global__ void transpose_in_kernel(const float* __restrict__ x, float* __restrict__ X)
{
    __shared__ float tile[32][33];
    int bh = blockIdx.z; int b = bh / HH, h = bh % HH;
    int w0 = blockIdx.x * 32, c0 = blockIdx.y * 32;
#pragma unroll
    for (int r = 0; r < 4; r++) {
        int c = c0 + threadIdx.y + r * 8;
        tile[threadIdx.y + r * 8][threadIdx.x] =
            x[(((size_t)b * CH + c) * HH + h) * WW + w0 + threadIdx.x];
    }
    __syncthreads();
#pragma unroll
    for (int r = 0; r < 4; r++) {
        int w = w0 + threadIdx.y + r * 8;
        X[(((size_t)b * HH + h) * WW + w) * CH + c0 + threadIdx.x] =
            tile[threadIdx.x][threadIdx.y + r * 8];
    }
}

__global__ void transpose_out_kernel(const float* __restrict__ X, float* __restrict__ out)
{
    __shared__ float tile[32][33];
    int bh = blockIdx.z; int b = bh / HH, h = bh % HH;
    int w0 = blockIdx.x * 32, c0 = blockIdx.y * 32;
#pragma unroll
    for (int r = 0; r < 4; r++) {
        int w = w0 + threadIdx.y + r * 8;
        tile[threadIdx.y + r * 8][threadIdx.x] =
            X[(((size_t)b * HH + h) * WW + w) * CH + c0 + threadIdx.x];
    }
    __syncthreads();
#pragma unroll
    for (int r = 0; r < 4; r++) {
        int c = c0 + threadIdx.y + r * 8;
        out[(((size_t)b * CH + c) * HH + h) * WW + w0 + threadIdx.x] =
            tile[threadIdx.x][threadIdx.y + r * 8];
    }
}

// ---------------------------------------------------------------------------
// Row LayerNorm (C=512); fp32 in, fp16 out (feeds GEMMs only)
// ---------------------------------------------------------------------------
__global__ void ln_kernel(const float* __restrict__ X, __half* __restrict__ Y,
                          const float* __restrict__ g, const float* __restrict__ b)
{
    __shared__ float red[8];
    size_t t = blockIdx.x;
    float4 v = ((const float4*)(X + t * CH))[threadIdx.x];
    float s = v.x + v.y + v.z + v.w;
    float q = v.x * v.x + v.y * v.y + v.z * v.z + v.w * v.w;
#pragma unroll
    for (int o = 16; o > 0; o >>= 1) {
        s += __shfl_xor_sync(0xffffffffu, s, o);
        q += __shfl_xor_sync(0xffffffffu, q, o);
    }
    int warp = threadIdx.x >> 5;
    if ((threadIdx.x & 31) == 0) { red[warp] = s; red[warp + 4] = q; }
    __syncthreads();
    s = red[0] + red[1] + red[2] + red[3];
    q = red[4] + red[5] + red[6] + red[7];
    float mean = s * (1.0f / CH);
    float var  = q * (1.0f / CH) - mean * mean;
    float rs = rsqrtf(var + 1e-5f);
    float4 gg = ((const float4*)g)[threadIdx.x];
    float4 bb = ((const float4*)b)[threadIdx.x];
    __half2* Yp = (__half2*)(Y + t * CH);
    Yp[2 * threadIdx.x]     = __floats2half2_rn((v.x - mean) * rs * gg.x + bb.x,
                                                (v.y - mean) * rs * gg.y + bb.y);
    Yp[2 * threadIdx.x + 1] = __floats2half2_rn((v.z - mean) * rs * gg.z + bb.z,
                                                (v.w - mean) * rs * gg.w + bb.w);
}

// ---------------------------------------------------------------------------
// Shared mma helpers
// ---------------------------------------------------------------------------
__device__ __forceinline__ void cp16(uint32_t dst, const void* src) {
    asm volatile("cp.async.cg.shared.global [%0], [%1], 16;" :: "r"(dst), "l"(src));
}

#define LDSM_X4(R, addr) \
    asm volatile("ldmatrix.sync.aligned.m8n8.x4.shared.b16 {%0,%1,%2,%3}, [%4];" \
                 : "=r"((R)[0]), "=r"((R)[1]), "=r"((R)[2]), "=r"((R)[3]) : "r"(addr))

#define LDSM_X4_T(R, addr) \
    asm volatile("ldmatrix.sync.aligned.m8n8.x4.trans.shared.b16 {%0,%1,%2,%3}, [%4];" \
                 : "=r"((R)[0]), "=r"((R)[1]), "=r"((R)[2]), "=r"((R)[3]) : "r"(addr))

__device__ __forceinline__ void mma16816(float* c, const uint32_t* a, const uint32_t* b) {
    asm volatile(
        "mma.sync.aligned.m16n8k16.row.col.f32.f16.f16.f32 "
        "{%0,%1,%2,%3}, {%4,%5,%6,%7}, {%8,%9}, {%0,%1,%2,%3};"
        : "+f"(c[0]), "+f"(c[1]), "+f"(c[2]), "+f"(c[3])
        : "r"(a[0]), "r"(a[1]), "r"(a[2]), "r"(a[3]), "r"(b[0]), "r"(b[1]));
}

__device__ __forceinline__ float warpMaxf(float v) {
#pragma unroll
    for (int o = 16; o > 0; o >>= 1) v = fmaxf(v, __shfl_xor_sync(0xffffffffu, v, o));
    return v;
}
__device__ __forceinline__ float warpSumf(float v) {
#pragma unroll
    for (int o = 16; o > 0; o >>= 1) v += __shfl_xor_sync(0xffffffffu, v, o);
    return v;
}

// ---------------------------------------------------------------------------
// fp16 mma.sync GEMM: C[M,Nn] = A[M,K] @ W[Nn,K]^T (NT, K-contiguous halves)
// 128x128x64 CTA tile, 8 warps x (64x32), 3-stage cp.async pipeline,
// single __syncthreads per chunk.
// ---------------------------------------------------------------------------
#define GEMM_SMEM 98304   // A[3]:48KB + B[3]:48KB (128 rows x 128B per stage)

template<bool PERM, bool HAS_BIAS, bool RELU, bool ACCUM, bool OUT_HALF>
__global__ __launch_bounds__(256, 2)
void mma_gemm(const __half* __restrict__ A, const __half* __restrict__ Wt,
              const float* __restrict__ bias, void* __restrict__ CdV,
              int M, int Nn, int K)
{
    extern __shared__ char smc[];
    uint32_t sA0 = (uint32_t)__cvta_generic_to_shared(smc);   // 3 x 16KB
    uint32_t sB0 = sA0 + 49152;                               // 3 x 16KB

    const int tid  = threadIdx.x;
    const int wid  = tid >> 5, lane = tid & 31;
    const int gid  = lane >> 2, tg = lane & 3;
    const int l8   = lane & 7,  sub = lane >> 3;
    const int m0   = blockIdx.y * 128, n0 = blockIdx.x * 128;
    const int wm   = (wid >> 2) * 64;
    const int wn   = (wid & 3) * 32;

    float acc[4][4][4];
#pragma unroll
    for (int mi = 0; mi < 4; mi++)
#pragma unroll
        for (int ni = 0; ni < 4; ni++)
#pragma unroll
            for (int r = 0; r < 4; r++) acc[mi][ni][r] = 0.0f;

    const int NC = K >> 6;   // 64-half chunks (always >= 2 here)

    auto loadTiles = [&](int buf, int kc) {
#pragma unroll
        for (int l = 0; l < 4; l++) {
            int idx = tid + l * 256;
            int row = idx >> 3, c = idx & 7;
            uint32_t d = sA0 + (uint32_t)(buf * 16384 + row * 128 + ((c ^ (row & 7)) << 4));
            cp16(d, A + (size_t)(m0 + row) * K + kc + c * 8);
        }
#pragma unroll
        for (int l = 0; l < 4; l++) {
            int idx = tid + l * 256;
            int row = idx >> 3, c = idx & 7;
            int j = n0 + row;
            int wr = PERM ? ((j & 511) * 3 + (j >> 9)) : j;
            uint32_t d = sB0 + (uint32_t)(buf * 16384 + row * 128 + ((c ^ (row & 7)) << 4));
            cp16(d, Wt + (size_t)wr * K + kc + c * 8);
        }
    };

    // prologue: stages 0 and 1 in flight
    loadTiles(0, 0);
    asm volatile("cp.async.commit_group;");
    loadTiles(1, 64);
    asm volatile("cp.async.commit_group;");

    int buf = 0;
    for (int c = 0; c < NC; c++) {
        asm volatile("cp.async.wait_group 1;" ::: "memory");  // stage c resident
        __syncthreads();
        if (c + 2 < NC) {
            int nb = buf + 2; if (nb >= 3) nb -= 3;
            loadTiles(nb, (c + 2) << 6);
            asm volatile("cp.async.commit_group;");
        } else {
            // keep group accounting uniform so wait_group 1 drains correctly
            asm volatile("cp.async.commit_group;");
        }

        uint32_t aB = sA0 + buf * 16384;
        uint32_t bB = sB0 + buf * 16384;
#pragma unroll
        for (int ks = 0; ks < 4; ks++) {
            uint32_t a[4][4], b[2][4];
            int cA = (2 * ks + (sub >> 1)) ^ l8;
#pragma unroll
            for (int mi = 0; mi < 4; mi++) {
                int row = wm + mi * 16 + ((sub & 1) << 3) + l8;
                LDSM_X4(a[mi], aB + (uint32_t)(row * 128 + (cA << 4)));
            }
            int cB = (2 * ks + (sub & 1)) ^ l8;
#pragma unroll
            for (int nq = 0; nq < 2; nq++) {
                int row = wn + nq * 16 + ((sub >> 1) << 3) + l8;
                LDSM_X4(b[nq], bB + (uint32_t)(row * 128 + (cB << 4)));
            }
#pragma unroll
            for (int mi = 0; mi < 4; mi++)
#pragma unroll
                for (int ni = 0; ni < 4; ni++)
                    mma16816(acc[mi][ni], a[mi], &b[ni >> 1][(ni & 1) * 2]);
        }
        if (++buf == 3) buf = 0;
    }

#pragma unroll
    for (int ni = 0; ni < 4; ni++) {
        int col = n0 + wn + ni * 8 + 2 * tg;
        float2 bv = make_float2(0.f, 0.f);
        if (HAS_BIAS) bv = *(const float2*)(bias + col);
#pragma unroll
        for (int mi = 0; mi < 4; mi++) {
            int row0 = m0 + wm + mi * 16 + gid;
#pragma unroll
            for (int h = 0; h < 2; h++) {
                int row = row0 + h * 8;
                float vx = acc[mi][ni][2 * h + 0];
                float vy = acc[mi][ni][2 * h + 1];
                if (HAS_BIAS) { vx += bv.x; vy += bv.y; }
                if (RELU) { vx = fmaxf(vx, 0.f); vy = fmaxf(vy, 0.f); }
                size_t off = (size_t)row * Nn + col;
                if (OUT_HALF) {
                    *(__half2*)((__half*)CdV + off) = __floats2half2_rn(vx, vy);
                } else {
                    float* Cd = (float*)CdV;
                    float2 o;
                    if (ACCUM) {
                        o = *(const float2*)(Cd + off);
                        o.x += vx; o.y += vy;
                    } else {
                        o = make_float2(vx, vy);
                    }
                    *(float2*)(Cd + off) = o;
                }
            }
        }
    }
}

// ---------------------------------------------------------------------------
// W-axis attention (L=192), tensor-core flash-style.
// 2 CTAs per (b,h), 96 queries each, 256 threads / 8 warps.
// Pass1: S = QK^T (fp16 S, pitch 400B). Softmax fp32 in-place. Pass2: P@V.
// ---------------------------------------------------------------------------
#define WSM_Q 0
#define WSM_K 12288
#define WSM_S 36864        // 96 rows x 400B = 38400
#define WSM_TOTAL 75264
#define SCALE_ATTN 0.04419417382415922f  // 1/sqrt(512)

__global__ __launch_bounds__(256, 2)
void attn_w_mma(const __half* __restrict__ qkv, __half* __restrict__ ctx)
{
    extern __shared__ char wsm[];
    uint32_t sb = (uint32_t)__cvta_generic_to_shared(wsm);
    const uint32_t sQ = sb + WSM_Q, sK = sb + WSM_K, sS = sb + WSM_S, sV = sb;

    const int tid = threadIdx.x;
    const int wid = tid >> 5, lane = tid & 31;
    const int gid = lane >> 2, tg = lane & 3;
    const int l8  = lane & 7,  sub = lane >> 3;
    const size_t base = (size_t)blockIdx.y * WW;
    const int q0 = blockIdx.x * 96;
    const int wm = (wid >> 2) * 48;       // {0,48}
    const int wn = (wid & 3) * 48;        // {0,48,96,144}

    float acc[3][6][4];
#pragma unroll
    for (int mi = 0; mi < 3; mi++)
#pragma unroll
        for (int ni = 0; ni < 6; ni++)
#pragma unroll
            for (int r = 0; r < 4; r++) acc[mi][ni][r] = 0.0f;

    // ---- Pass 1: S = Q K^T over kc chunks of 64 ----
    for (int kc = 0; kc < CH; kc += 64) {
#pragma unroll
        for (int l = 0; l < 3; l++) {                 // Q: 96 rows x 8 chunks
            int idx = tid + l * 256;
            int row = idx >> 3, c = idx & 7;
            cp16(sQ + (uint32_t)(row * 128 + ((c ^ (row & 7)) << 4)),
                 qkv + (base + q0 + row) * C3 + kc + c * 8);
        }
#pragma unroll
        for (int l = 0; l < 6; l++) {                 // K: 192 rows x 8 chunks
            int idx = tid + l * 256;
            int row = idx >> 3, c = idx & 7;
            cp16(sK + (uint32_t)(row * 128 + ((c ^ (row & 7)) << 4)),
                 qkv + (base + row) * C3 + CH + kc + c * 8);
        }
        asm volatile("cp.async.commit_group;");
        asm volatile("cp.async.wait_group 0;" ::: "memory");
        __syncthreads();
#pragma unroll
        for (int ks = 0; ks < 4; ks++) {
            uint32_t a[3][4], b[3][4];
            int cA = (2 * ks + (sub >> 1)) ^ l8;
#pragma unroll
            for (int mi = 0; mi < 3; mi++) {
                int row = wm + mi * 16 + ((sub & 1) << 3) + l8;
                LDSM_X4(a[mi], sQ + (uint32_t)(row * 128 + (cA << 4)));
            }
            int cB = (2 * ks + (sub & 1)) ^ l8;
#pragma unroll
            for (int nq = 0; nq < 3; nq++) {
                int row = wn + nq * 16 + ((sub >> 1) << 3) + l8;
                LDSM_X4(b[nq], sK + (uint32_t)(row * 128 + (cB << 4)));
            }
#pragma unroll
            for (int mi = 0; mi < 3; mi++)
#pragma unroll
                for (int ni = 0; ni < 6; ni++)
                    mma16816(acc[mi][ni], a[mi], &b[ni >> 1][(ni & 1) * 2]);
        }
        __syncthreads();
    }
    // write S (fp16, pitch 400B)
#pragma unroll
    for (int mi = 0; mi < 3; mi++)
#pragma unroll
        for (int ni = 0; ni < 6; ni++) {
            int row = wm + mi * 16 + gid;
            int col = wn + ni * 8 + 2 * tg;
            *(__half2*)(wsm + WSM_S + (size_t)row * 400 + col * 2) =
                __floats2half2_rn(acc[mi][ni][0] * SCALE_ATTN, acc[mi][ni][1] * SCALE_ATTN);
            *(__half2*)(wsm + WSM_S + (size_t)(row + 8) * 400 + col * 2) =
                __floats2half2_rn(acc[mi][ni][2] * SCALE_ATTN, acc[mi][ni][3] * SCALE_ATTN);
        }
    __syncthreads();

    // ---- Softmax (fp32 math, fp16 in place) ----
    for (int r = wid; r < 96; r += 8) {
        __half* Srow = (__half*)(wsm + WSM_S + (size_t)r * 400);
        float mx = -1e30f;
#pragma unroll
        for (int it = 0; it < 6; it++) mx = fmaxf(mx, __half2float(Srow[lane + it * 32]));
        mx = warpMaxf(mx);
        float e[6], sm = 0.0f;
#pragma unroll
        for (int it = 0; it < 6; it++) {
            e[it] = __expf(__half2float(Srow[lane + it * 32]) - mx);
            sm += e[it];
        }
        sm = warpSumf(sm);
        float inv = 1.0f / sm;
#pragma unroll
        for (int it = 0; it < 6; it++) Srow[lane + it * 32] = __float2half(e[it] * inv);
    }
    __syncthreads();

    // ---- Pass 2: ctx = P @ V, 64 ctx cols per pass (V aliases Q/K region) ----
    const int wn2 = (wid & 3) * 16;
    for (int c0 = 0; c0 < CH; c0 += 64) {
#pragma unroll
        for (int l = 0; l < 6; l++) {                 // V: 192 rows x 8 chunks
            int idx = tid + l * 256;
            int row = idx >> 3, c = idx & 7;
            cp16(sV + (uint32_t)(row * 128 + ((c ^ (row & 7)) << 4)),
                 qkv + (base + row) * C3 + 2 * CH + c0 + c * 8);
        }
        asm volatile("cp.async.commit_group;");
        asm volatile("cp.async.wait_group 0;" ::: "memory");
        __syncthreads();

        float acc2[3][2][4];
#pragma unroll
        for (int mi = 0; mi < 3; mi++)
#pragma unroll
            for (int ni = 0; ni < 2; ni++)
#pragma unroll
                for (int r = 0; r < 4; r++) acc2[mi][ni][r] = 0.0f;

#pragma unroll 4
        for (int kb = 0; kb < 12; kb++) {
            uint32_t a[3][4], v[4];
            int cA = 2 * kb + (sub >> 1);             // P: no swizzle (pitch 400)
#pragma unroll
            for (int mi = 0; mi < 3; mi++) {
                int row = wm + mi * 16 + ((sub & 1) << 3) + l8;
                LDSM_X4(a[mi], sS + (uint32_t)(row * 400 + (cA << 4)));
            }
            int rowv = kb * 16 + ((sub & 1) << 3) + l8;
            int cV = ((wn2 >> 3) + (sub >> 1)) ^ l8;
            LDSM_X4_T(v, sV + (uint32_t)(rowv * 128 + (cV << 4)));
#pragma unroll
            for (int mi = 0; mi < 3; mi++)
#pragma unroll
                for (int ni = 0; ni < 2; ni++)
                    mma16816(acc2[mi][ni], a[mi], &v[ni * 2]);
        }
        __syncthreads();
#pragma unroll
        for (int mi = 0; mi < 3; mi++)
#pragma unroll
            for (int ni = 0; ni < 2; ni++) {
                int row = wm + mi * 16 + gid;
                int col = c0 + wn2 + ni * 8 + 2 * tg;
                size_t t0 = base + q0 + row;
                *(__half2*)&ctx[t0 * CH + col] =
                    __floats2half2_rn(acc2[mi][ni][0], acc2[mi][ni][1]);
                *(__half2*)&ctx[(t0 + 8) * CH + col] =
                    __floats2half2_rn(acc2[mi][ni][2], acc2[mi][ni][3]);
            }
    }
}

// ---------------------------------------------------------------------------
// H-axis attention (L=48), tensor-core. One CTA per (b,w), 128 thr / 4 warps.
// K/V padded to 64 rows (pad rows zeroed once). S fp16 swizzled 128B rows.
// ---------------------------------------------------------------------------
__global__ __launch_bounds__(128)
void attn_h_mma(const __half* __restrict__ qkv, __half* __restrict__ ctx)
{
    __shared__ __align__(16) char hsm[28672];
    // Q: 0..6144 (48x128B), K: 6144..14336 (64x128B),
    // S: 14336..20480 (48x128B), V: 20480..28672 (64x128B)
    uint32_t sb = (uint32_t)__cvta_generic_to_shared(hsm);
    const uint32_t sQ = sb, sK = sb + 6144, sS = sb + 14336, sV = sb + 20480;

    const int tid = threadIdx.x;
    const int wid = tid >> 5, lane = tid & 31;
    const int gid = lane >> 2, tg = lane & 3;
    const int l8  = lane & 7,  sub = lane >> 3;
    const int b   = blockIdx.x / WW, w = blockIdx.x % WW;
    const size_t base = (size_t)b * HH * WW + w;
    const int wn = wid * 16;

    // zero pad rows 48-63 of K and V (never overwritten by loads)
    {
        uint4 z = make_uint4(0, 0, 0, 0);
        ((uint4*)(hsm + 6144 + 48 * 128))[tid]  = z;   // 2048B = 128 x 16B
        ((uint4*)(hsm + 20480 + 48 * 128))[tid] = z;
    }

    float acc[3][2][4];
#pragma unroll
    for (int mi = 0; mi < 3; mi++)
#pragma unroll
        for (int ni = 0; ni < 2; ni++)
#pragma unroll
            for (int r = 0; r < 4; r++) acc[mi][ni][r] = 0.0f;

    // ---- Pass 1 ----
    for (int kc = 0; kc < CH; kc += 64) {
#pragma unroll
        for (int l = 0; l < 3; l++) {                 // Q: 48 rows x 8 chunks
            int idx = tid + l * 128;
            int row = idx >> 3, c = idx & 7;
            cp16(sQ + (uint32_t)(row * 128 + ((c ^ (row & 7)) << 4)),
                 qkv + (base + (size_t)row * WW) * C3 + kc + c * 8);
        }
#pragma unroll
        for (int l = 0; l < 3; l++) {                 // K: 48 rows x 8 chunks
            int idx = tid + l * 128;
            int row = idx >> 3, c = idx & 7;
            cp16(sK + (uint32_t)(row * 128 + ((c ^ (row & 7)) << 4)),
                 qkv + (base + (size_t)row * WW) * C3 + CH + kc + c * 8);
        }
        asm volatile("cp.async.commit_group;");
        asm volatile("cp.async.wait_group 0;" ::: "memory");
        __syncthreads();
#pragma unroll
        for (int ks = 0; ks < 4; ks++) {
            uint32_t a[3][4], bfr[4];
            int cA = (2 * ks + (sub >> 1)) ^ l8;
#pragma unroll
            for (int mi = 0; mi < 3; mi++) {
                int row = mi * 16 + ((sub & 1) << 3) + l8;
                LDSM_X4(a[mi], sQ + (uint32_t)(row * 128 + (cA << 4)));
            }
            int cB = (2 * ks + (sub & 1)) ^ l8;
            int rowb = wn + ((sub >> 1) << 3) + l8;
            LDSM_X4(bfr, sK + (uint32_t)(rowb * 128 + (cB << 4)));
#pragma unroll
            for (int mi = 0; mi < 3; mi++)
#pragma unroll
                for (int ni = 0; ni < 2; ni++)
                    mma16816(acc[mi][ni], a[mi], &bfr[ni * 2]);
        }
        __syncthreads();
    }
    // write S fp16 swizzled (cols 48-63 are zeros from zero-padded K)
#pragma unroll
    for (int mi = 0; mi < 3; mi++)
#pragma unroll
        for (int ni = 0; ni < 2; ni++) {
            int col = wn + ni * 8 + 2 * tg;
            int chunk = col >> 3, coff = (col & 7) * 2;
#pragma unroll
            for (int h = 0; h < 2; h++) {
                int row = mi * 16 + gid + h * 8;
                *(__half2*)(hsm + 14336 + row * 128 + ((chunk ^ (row & 7)) << 4) + coff) =
                    __floats2half2_rn(acc[mi][ni][2 * h] * SCALE_ATTN,
                                      acc[mi][ni][2 * h + 1] * SCALE_ATTN);
            }
        }
    __syncthreads();

    // ---- Softmax over j<48 (cols 48-63 stay exactly 0) ----
    for (int r = wid; r < 48; r += 4) {
        char* Sr = hsm + 14336 + r * 128;
        int s7 = r & 7;
        float mx = -1e30f, e0 = 0.f, e1 = 0.f;
        {
            int j = lane;
            mx = __half2float(*(__half*)(Sr + (((j >> 3) ^ s7) << 4) + (j & 7) * 2));
            if (lane < 16) {
                j = lane + 32;
                mx = fmaxf(mx, __half2float(*(__half*)(Sr + (((j >> 3) ^ s7) << 4) + (j & 7) * 2)));
            }
        }
        mx = warpMaxf(mx);
        {
            int j = lane;
            e0 = __expf(__half2float(*(__half*)(Sr + (((j >> 3) ^ s7) << 4) + (j & 7) * 2)) - mx);
            if (lane < 16) {
                j = lane + 32;
                e1 = __expf(__half2float(*(__half*)(Sr + (((j >> 3) ^ s7) << 4) + (j & 7) * 2)) - mx);
            }
        }
        float sm = warpSumf(e0 + e1);
        float inv = 1.0f / sm;
        {
            int j = lane;
            *(__half*)(Sr + (((j >> 3) ^ s7) << 4) + (j & 7) * 2) = __float2half(e0 * inv);
            if (lane < 16) {
                j = lane + 32;
                *(__half*)(Sr + (((j >> 3) ^ s7) << 4) + (j & 7) * 2) = __float2half(e1 * inv);
            }
        }
    }
    __syncthreads();

    // ---- Pass 2: ctx = P @ V over 64-col passes ----
    for (int c0 = 0; c0 < CH; c0 += 64) {
#pragma unroll
        for (int l = 0; l < 3; l++) {                 // V: 48 rows x 8 chunks
            int idx = tid + l * 128;
            int row = idx >> 3, c = idx & 7;
            cp16(sV + (uint32_t)(row * 128 + ((c ^ (row & 7)) << 4)),
                 qkv + (base + (size_t)row * WW) * C3 + 2 * CH + c0 + c * 8);
        }
        asm volatile("cp.async.commit_group;");
        asm volatile("cp.async.wait_group 0;" ::: "memory");
        __syncthreads();

        float acc2[3][2][4];
#pragma unroll
        for (int mi = 0; mi < 3; mi++)
#pragma unroll
            for (int ni = 0; ni < 2; ni++)
#pragma unroll
                for (int r = 0; r < 4; r++) acc2[mi][ni][r] = 0.0f;

#pragma unroll
        for (int kb = 0; kb < 4; kb++) {
            uint32_t a[3][4], v[4];
            int cA = (2 * kb + (sub >> 1)) ^ l8;      // S swizzled
#pragma unroll
            for (int mi = 0; mi < 3; mi++) {
                int row = mi * 16 + ((sub & 1) << 3) + l8;
                LDSM_X4(a[mi], sS + (uint32_t)(row * 128 + (cA << 4)));
            }
            int rowv = kb * 16 + ((sub & 1) << 3) + l8;
            int cV = ((wn >> 3) + (sub >> 1)) ^ l8;
            LDSM_X4_T(v, sV + (uint32_t)(rowv * 128 + (cV << 4)));
#pragma unroll
            for (int mi = 0; mi < 3; mi++)
#pragma unroll
                for (int ni = 0; ni < 2; ni++)
                    mma16816(acc2[mi][ni], a[mi], &v[ni * 2]);
        }
        __syncthreads();
#pragma unroll
        for (int mi = 0; mi < 3; mi++)
#pragma unroll
            for (int ni = 0; ni < 2; ni++) {
                int col = c0 + wn + ni * 8 + 2 * tg;
#pragma unroll
                for (int h = 0; h < 2; h++) {
                    int row = mi * 16 + gid + h * 8;
                    size_t t = base + (size_t)row * WW;
                    *(__half2*)&ctx[t * CH + col] =
                        __floats2half2_rn(acc2[mi][ni][2 * h], acc2[mi][ni][2 * h + 1]);
                }
            }
    }
}

// ---------------------------------------------------------------------------
// Launch
// ---------------------------------------------------------------------------
extern "C" void kernel_launch(void* const* d_in, const int* in_sizes, int n_in,
                              void* d_out, int out_size)
{
    const float* x      = (const float*)d_in[0];
    const float* w_qkv1 = (const float*)d_in[1];
    const float* w_out1 = (const float*)d_in[2];
    const float* w_qkv2 = (const float*)d_in[3];
    const float* w_out2 = (const float*)d_in[4];
    const float* g1 = (const float*)d_in[5],  *b1 = (const float*)d_in[6];
    const float* g2 = (const float*)d_in[7],  *b2 = (const float*)d_in[8];
    const float* g3 = (const float*)d_in[9],  *b3 = (const float*)d_in[10];
    const float* w_fc1 = (const float*)d_in[11], *b_fc1 = (const float*)d_in[12];
    const float* w_fc2 = (const float*)d_in[13], *b_fc2 = (const float*)d_in[14];
    float* out = (float*)d_out;

    float *X; __half *LN, *QKV, *CTX, *Hb, *WR;
    cudaGetSymbolAddress((void**)&X,   g_x);
    cudaGetSymbolAddress((void**)&LN,  g_ln);
    cudaGetSymbolAddress((void**)&QKV, g_qkv);
    cudaGetSymbolAddress((void**)&CTX, g_ctx);
    cudaGetSymbolAddress((void**)&Hb,  g_h);
    cudaGetSymbolAddress((void**)&WR,  g_wr);

    cudaFuncSetAttribute(mma_gemm<true,  false, false, false, true >,
                         cudaFuncAttributeMaxDynamicSharedMemorySize, GEMM_SMEM);
    cudaFuncSetAttribute(mma_gemm<false, false, false, true,  false>,
                         cudaFuncAttributeMaxDynamicSharedMemorySize, GEMM_SMEM);
    cudaFuncSetAttribute(mma_gemm<false, true,  true,  false, true >,
                         cudaFuncAttributeMaxDynamicSharedMemorySize, GEMM_SMEM);
    cudaFuncSetAttribute(mma_gemm<false, true,  false, true,  false>,
                         cudaFuncAttributeMaxDynamicSharedMemorySize, GEMM_SMEM);
    cudaFuncSetAttribute(attn_w_mma,
                         cudaFuncAttributeMaxDynamicSharedMemorySize, WSM_TOTAL);

    // fp16 weight conversion (graph-capturable kernels)
    f2h_kernel<<<(C3*CH/4 + 255)/256, 256>>>(w_qkv1, WR + O_WQ1, C3*CH/4);
    f2h_kernel<<<(CH*CH/4 + 255)/256, 256>>>(w_out1, WR + O_WO1, CH*CH/4);
    f2h_kernel<<<(C3*CH/4 + 255)/256, 256>>>(w_qkv2, WR + O_WQ2, C3*CH/4);
    f2h_kernel<<<(CH*CH/4 + 255)/256, 256>>>(w_out2, WR + O_WO2, CH*CH/4);
    f2h_kernel<<<(C4*CH/4 + 255)/256, 256>>>(w_fc1,  WR + O_FC1, C4*CH/4);
    f2h_kernel<<<(CH*C4/4 + 255)/256, 256>>>(w_fc2,  WR + O_FC2, CH*C4/4);

    dim3 tb(32, 8);
    dim3 tgrid(WW / 32, CH / 32, NB * HH);

    transpose_in_kernel<<<tgrid, tb>>>(x, X);

    // Block 1: attention along H
    ln_kernel<<<NTOK, 128>>>(X, LN, g1, b1);
    mma_gemm<true,  false, false, false, true ><<<dim3(C3 / 128, NTOK / 128), 256, GEMM_SMEM>>>(LN, WR + O_WQ1, nullptr, QKV, NTOK, C3, CH);
    attn_h_mma<<<NB * WW, 128>>>(QKV, CTX);
    mma_gemm<false, false, false, true,  false><<<dim3(CH / 128, NTOK / 128), 256, GEMM_SMEM>>>(CTX, WR + O_WO1, nullptr, X, NTOK, CH, CH);

    // Block 2: attention along W
    ln_kernel<<<NTOK, 128>>>(X, LN, g2, b2);
    mma_gemm<true,  false, false, false, true ><<<dim3(C3 / 128, NTOK / 128), 256, GEMM_SMEM>>>(LN, WR + O_WQ2, nullptr, QKV, NTOK, C3, CH);
    attn_w_mma<<<dim3(2, NB * HH), 256, WSM_TOTAL>>>(QKV, CTX);
    mma_gemm<false, false, false, true,  false><<<dim3(CH / 128, NTOK / 128), 256, GEMM_SMEM>>>(CTX, WR + O_WO2, nullptr, X, NTOK, CH, CH);

    // MLP
    ln_kernel<<<NTOK, 128>>>(X, LN, g3, b3);
    mma_gemm<false, true,  true,  false, true ><<<dim3(C4 / 128, NTOK / 128), 256, GEMM_SMEM>>>(LN, WR + O_FC1, b_fc1, Hb, NTOK, C4, CH);
    mma_gemm<false, true,  false, true,  false><<<dim3(CH / 128, NTOK / 128), 256, GEMM_SMEM>>>(Hb, WR + O_FC2, b_fc2, X, NTOK, CH, C4);

    transpose_out_kernel<<<tgrid, tb>>>(X, out);
}